// round 13
// baseline (speedup 1.0000x reference)
#include <cuda_runtime.h>
#include <cuda_bf16.h>
#include <math.h>
#include <stdint.h>

// ---------------- problem constants ----------------
#define NTOK  49152
#define NSEQ  2048
#define Bdim  16
#define Tdim  128
#define Jm    24
#define Hdim  256
#define H3    768
#define H4    1024
#define Lnum  4
#define Mnum  12
#define RANKv 8
#define HEADS 8
#define DH    32
#define TOKPB 3072

__constant__ int c_nj[Mnum] = {8,10,12,14,16,18,20,22,24,9,13,17};

// ---------------- scratch ----------------
__device__ float         g_x   [(size_t)NTOK * Hdim];
__device__ __nv_bfloat16 g_h   [(size_t)NTOK * Hdim];
__device__ __nv_bfloat16 g_qkv [(size_t)NTOK * H3 ];
__device__ __nv_bfloat16 g_o   [(size_t)NTOK * Hdim];
__device__ __nv_bfloat16 g_midb[(size_t)NTOK * H4 ];
__device__ float         g_tmp [(size_t)NTOK * RANKv];
__device__ __nv_bfloat16 g_wt  [(size_t)Lnum * 786432];
__device__ int           g_cat [Bdim * Jm];

// ---------------- helpers ----------------
__device__ __forceinline__ uint32_t smem_u32(const void* p) {
    uint32_t a;
    asm("{ .reg .u64 t; cvta.to.shared.u64 t, %1; cvt.u32.u64 %0, t; }" : "=r"(a) : "l"(p));
    return a;
}
__device__ __forceinline__ void cp16(uint32_t dst, const void* src) {
    asm volatile("cp.async.cg.shared.global [%0], [%1], 16;" :: "r"(dst), "l"(src));
}
__device__ __forceinline__ void cp_commit() { asm volatile("cp.async.commit_group;"); }
__device__ __forceinline__ void ldm_x4(uint32_t& r0, uint32_t& r1, uint32_t& r2, uint32_t& r3, uint32_t a) {
    asm volatile("ldmatrix.sync.aligned.m8n8.x4.shared.b16 {%0,%1,%2,%3}, [%4];"
                 : "=r"(r0), "=r"(r1), "=r"(r2), "=r"(r3) : "r"(a));
}
__device__ __forceinline__ void mma16816(float* c, const uint32_t* a, const uint32_t* b) {
    asm volatile("mma.sync.aligned.m16n8k16.row.col.f32.bf16.bf16.f32 "
                 "{%0,%1,%2,%3},{%4,%5,%6,%7},{%8,%9},{%0,%1,%2,%3};"
                 : "+f"(c[0]), "+f"(c[1]), "+f"(c[2]), "+f"(c[3])
                 : "r"(a[0]), "r"(a[1]), "r"(a[2]), "r"(a[3]), "r"(b[0]), "r"(b[1]));
}
__device__ __forceinline__ uint32_t pack2bf(float x, float y) {
    __nv_bfloat162 h = __floats2bfloat162_rn(x, y);
    return *reinterpret_cast<uint32_t*>(&h);
}
__device__ __forceinline__ float gelu_tanh(float x) {
    float x3 = x * x * x;
    return 0.5f * x * (1.f + tanhf(0.7978845608028654f * (x + 0.044715f * x3)));
}
__device__ __forceinline__ float4 ld4(const float* p, int c) { return *(const float4*)(p + c); }

// ================= kernel 1: 128x128 HMMA GEMM, compile-time K (R11 proven) =================
#define TILE2  16384
#define NSTG   3
#define GSMEM  (NSTG * 2 * TILE2)    // 98304

template<int EPI, int KT>
__global__ void __launch_bounds__(256, 2)
hmma_gemm_kernel(const __nv_bfloat16* __restrict__ A, const __nv_bfloat16* __restrict__ Bt,
                 __nv_bfloat16* __restrict__ Cb,
                 const float* __restrict__ bias,
                 const float* __restrict__ ltmp, const float* __restrict__ lB,
                 const int* __restrict__ midx,
                 int N)
{
    extern __shared__ char dynsm[];
    constexpr int NCH = KT >> 6;

    int tid = threadIdx.x, lane = tid & 31, wid = tid >> 5;
    int wm = wid & 1, wn = wid >> 1;
    int brow = blockIdx.y * 128, bcol = blockIdx.x * 128;

    float acc[4][4][4];
    #pragma unroll
    for (int i = 0; i < 4; i++)
        #pragma unroll
        for (int j = 0; j < 4; j++)
            #pragma unroll
            for (int q = 0; q < 4; q++) acc[i][j][q] = 0.f;

    int lrow = tid >> 3, lcc = tid & 7;
    uint32_t soff0 = (uint32_t)(lrow * 128 + ((lcc ^ (lrow & 7)) * 16));
    const __nv_bfloat16* Ap0 = A + (size_t)(brow + lrow) * KT + lcc * 8;
    const __nv_bfloat16* Bp0 = Bt + (size_t)(bcol + lrow) * KT + lcc * 8;
    uint32_t smbase = smem_u32(dynsm);

    auto load_tiles = [&](int ch, int stage) {
        uint32_t da = smbase + (uint32_t)((stage * 2 + 0) * TILE2) + soff0;
        uint32_t db = smbase + (uint32_t)((stage * 2 + 1) * TILE2) + soff0;
        const __nv_bfloat16* Ah = Ap0 + ch * 64;
        const __nv_bfloat16* Bh = Bp0 + ch * 64;
        #pragma unroll
        for (int hh = 0; hh < 4; hh++) {
            cp16(da + hh * 4096, Ah + hh * 32 * KT);
            cp16(db + hh * 4096, Bh + hh * 32 * KT);
        }
        cp_commit();
    };

    int rsel = lane & 15, ksel = lane >> 4;
    uint32_t abase[4], bbase[2];
    #pragma unroll
    for (int mf = 0; mf < 4; mf++) {
        int ar = wm * 64 + mf * 16 + rsel;
        abase[mf] = (uint32_t)(ar * 128 + (ar & 7) * 16);
    }
    #pragma unroll
    for (int nf2 = 0; nf2 < 2; nf2++) {
        int br = wn * 32 + nf2 * 16 + rsel;
        bbase[nf2] = (uint32_t)(br * 128 + (br & 7) * 16);
    }

    load_tiles(0, 0);
    load_tiles(1, 1);

    #pragma unroll
    for (int ch = 0; ch < NCH; ch++) {
        asm volatile("cp.async.wait_group 1;");
        __syncthreads();

        uint32_t sa = smbase + (uint32_t)(((ch % NSTG) * 2 + 0) * TILE2);
        uint32_t sb = smbase + (uint32_t)(((ch % NSTG) * 2 + 1) * TILE2);

        #pragma unroll
        for (int ks = 0; ks < 4; ks++) {
            uint32_t cx = (uint32_t)((ks * 2 + ksel) * 16);
            uint32_t a[4][4];
            #pragma unroll
            for (int mf = 0; mf < 4; mf++)
                ldm_x4(a[mf][0], a[mf][1], a[mf][2], a[mf][3], sa + (abase[mf] ^ cx));
            uint32_t b[4][2];
            #pragma unroll
            for (int nf2 = 0; nf2 < 2; nf2++) {
                uint32_t r0, r1, r2, r3;
                ldm_x4(r0, r1, r2, r3, sb + (bbase[nf2] ^ cx));
                b[nf2 * 2 + 0][0] = r0; b[nf2 * 2 + 0][1] = r2;
                b[nf2 * 2 + 1][0] = r1; b[nf2 * 2 + 1][1] = r3;
            }
            #pragma unroll
            for (int mf = 0; mf < 4; mf++)
                #pragma unroll
                for (int nf = 0; nf < 4; nf++)
                    mma16816(acc[mf][nf], a[mf], b[nf]);
        }

        if (ch + 2 < NCH) load_tiles(ch + 2, (ch + 2) % NSTG);
        else              cp_commit();
    }

    float* lb_s  = (float*)dynsm;
    float* tmp_s = (float*)(dynsm + 4096);
    if (EPI == 3) {
        __syncthreads();
        int m = midx[brow / TOKPB];
        #pragma unroll
        for (int hh = 0; hh < 4; hh++) {
            int i = tid + hh * 256;
            int q = i >> 7, c = i & 127;
            lb_s[q * 128 + c] = lB[((size_t)m * RANKv + q) * N + bcol + c];
            int r = i >> 3, q2 = i & 7;
            tmp_s[r * 9 + q2] = ltmp[(size_t)(brow + r) * RANKv + q2];
        }
        __syncthreads();
    }

    int g = lane >> 2, tg = lane & 3;
    #pragma unroll
    for (int mf = 0; mf < 4; mf++) {
        int rl = wm * 64 + mf * 16 + g;
        int r0 = brow + rl;
        #pragma unroll
        for (int nf = 0; nf < 4; nf++) {
            int cl  = wn * 32 + nf * 8 + tg * 2;
            int col = bcol + cl;
            float b0 = bias[col], b1 = bias[col + 1];
            float v0 = acc[mf][nf][0] + b0, v1 = acc[mf][nf][1] + b1;
            float v2 = acc[mf][nf][2] + b0, v3 = acc[mf][nf][3] + b1;
            if (EPI == 1) {
                *(uint32_t*)(Cb + (size_t)r0 * N + col)       = pack2bf(gelu_tanh(v0), gelu_tanh(v1));
                *(uint32_t*)(Cb + (size_t)(r0 + 8) * N + col) = pack2bf(gelu_tanh(v2), gelu_tanh(v3));
            } else {
                float a00 = 0.f, a01 = 0.f, a10 = 0.f, a11 = 0.f;
                #pragma unroll
                for (int q = 0; q < 8; q++) {
                    float w0 = lb_s[q * 128 + cl], w1 = lb_s[q * 128 + cl + 1];
                    float u0 = tmp_s[rl * 9 + q], u1 = tmp_s[(rl + 8) * 9 + q];
                    a00 += u0 * w0; a01 += u0 * w1;
                    a10 += u1 * w0; a11 += u1 * w1;
                }
                *(uint32_t*)(Cb + (size_t)r0 * N + col)       = pack2bf(v0 + a00, v1 + a01);
                *(uint32_t*)(Cb + (size_t)(r0 + 8) * N + col) = pack2bf(v2 + a10, v3 + a11);
            }
        }
    }
}

// ================= kernel 2: 64x256 HMMA GEMM + residual + fused LN (+ fused lora_tmp) ===========
#define TA64   8192
#define TB256  32768
#define STG64  (TA64 + TB256)        // 40960
#define GSMEM2 (2 * STG64)           // 81920

template<typename TO, int KT, int DOLORA>
__global__ void __launch_bounds__(256, 2)
hmma_ln_kernel(const __nv_bfloat16* __restrict__ A, const __nv_bfloat16* __restrict__ Bt,
               float* __restrict__ C,
               const float* __restrict__ bias, const float* __restrict__ gsc,
               const float* __restrict__ lnS, const float* __restrict__ lnB,
               TO* __restrict__ Hout,
               const float* __restrict__ lA, const int* __restrict__ midx,
               float* __restrict__ tmp)
{
    extern __shared__ char dynsm[];
    const int N = 256;
    constexpr int NCH = KT >> 6;

    int tid = threadIdx.x, lane = tid & 31, wid = tid >> 5;
    int wm = wid & 1, wn = wid >> 1;
    int brow = blockIdx.y * 64;

    float acc[2][8][4];
    #pragma unroll
    for (int i = 0; i < 2; i++)
        #pragma unroll
        for (int j = 0; j < 8; j++)
            #pragma unroll
            for (int q = 0; q < 4; q++) acc[i][j][q] = 0.f;

    int lrow = tid >> 3, lcc = tid & 7;
    uint32_t soff0 = (uint32_t)(lrow * 128 + ((lcc ^ (lrow & 7)) * 16));
    const __nv_bfloat16* Ap0 = A + (size_t)(brow + lrow) * KT + lcc * 8;
    const __nv_bfloat16* Bp0 = Bt + (size_t)lrow * KT + lcc * 8;
    uint32_t smbase = smem_u32(dynsm);

    auto load_tiles = [&](int ch, int stage) {
        uint32_t da = smbase + (uint32_t)(stage * STG64) + soff0;
        uint32_t db = da + TA64;
        const __nv_bfloat16* Ah = Ap0 + ch * 64;
        const __nv_bfloat16* Bh = Bp0 + ch * 64;
        #pragma unroll
        for (int hh = 0; hh < 2; hh++)
            cp16(da + hh * 4096, Ah + hh * 32 * KT);
        #pragma unroll
        for (int hh = 0; hh < 8; hh++)
            cp16(db + hh * 4096, Bh + hh * 32 * KT);
        cp_commit();
    };

    int rsel = lane & 15, ksel = lane >> 4;
    uint32_t abase[2], bbase[4];
    #pragma unroll
    for (int mf = 0; mf < 2; mf++) {
        int ar = wm * 32 + mf * 16 + rsel;
        abase[mf] = (uint32_t)(ar * 128 + (ar & 7) * 16);
    }
    #pragma unroll
    for (int nf2 = 0; nf2 < 4; nf2++) {
        int br = wn * 64 + nf2 * 16 + rsel;
        bbase[nf2] = (uint32_t)(br * 128 + (br & 7) * 16);
    }

    load_tiles(0, 0);

    for (int ch = 0; ch < NCH; ch++) {
        if (ch + 1 < NCH) {
            load_tiles(ch + 1, (ch + 1) & 1);
            asm volatile("cp.async.wait_group 1;");
        } else {
            asm volatile("cp.async.wait_group 0;");
        }
        __syncthreads();

        uint32_t sa = smbase + (uint32_t)((ch & 1) * STG64);
        uint32_t sb = sa + TA64;

        #pragma unroll
        for (int ks = 0; ks < 4; ks++) {
            uint32_t cx = (uint32_t)((ks * 2 + ksel) * 16);
            uint32_t a[2][4];
            #pragma unroll
            for (int mf = 0; mf < 2; mf++)
                ldm_x4(a[mf][0], a[mf][1], a[mf][2], a[mf][3], sa + (abase[mf] ^ cx));
            uint32_t b[8][2];
            #pragma unroll
            for (int nf2 = 0; nf2 < 4; nf2++) {
                uint32_t r0, r1, r2, r3;
                ldm_x4(r0, r1, r2, r3, sb + (bbase[nf2] ^ cx));
                b[nf2 * 2 + 0][0] = r0; b[nf2 * 2 + 0][1] = r2;
                b[nf2 * 2 + 1][0] = r1; b[nf2 * 2 + 1][1] = r3;
            }
            #pragma unroll
            for (int mf = 0; mf < 2; mf++)
                #pragma unroll
                for (int nf = 0; nf < 8; nf++)
                    mma16816(acc[mf][nf], a[mf], b[nf]);
        }
        __syncthreads();
    }

    int g = lane >> 2, tg = lane & 3;

    // residual rmw; updated x stays in acc
    #pragma unroll
    for (int mf = 0; mf < 2; mf++) {
        int r0 = brow + wm * 32 + mf * 16 + g;
        #pragma unroll
        for (int nf = 0; nf < 8; nf++) {
            int col = wn * 64 + nf * 8 + tg * 2;
            float b0 = bias[col], b1 = bias[col + 1];
            float s0 = gsc[col],  s1 = gsc[col + 1];
            float2 o0 = *(float2*)(C + (size_t)r0 * N + col);
            float2 o1 = *(float2*)(C + (size_t)(r0 + 8) * N + col);
            o0.x += s0 * (acc[mf][nf][0] + b0); o0.y += s1 * (acc[mf][nf][1] + b1);
            o1.x += s0 * (acc[mf][nf][2] + b0); o1.y += s1 * (acc[mf][nf][3] + b1);
            *(float2*)(C + (size_t)r0 * N + col)       = o0;
            *(float2*)(C + (size_t)(r0 + 8) * N + col) = o1;
            acc[mf][nf][0] = o0.x; acc[mf][nf][1] = o0.y;
            acc[mf][nf][2] = o1.x; acc[mf][nf][3] = o1.y;
        }
    }

    // smem layout for stats (+ optional lora staging)
    float* ssum = (float*)dynsm;         // [64][4]
    float* ssq  = ssum + 256;            // [64][4]
    float* smu  = ssq + 256;             // [64]
    float* srs  = smu + 64;              // [64]
    float* laS  = srs + 64;              // [256][8]  (DOLORA)
    float* red  = laS + 2048;            // [64][8][4] (DOLORA)
    __syncthreads();

    // LN statistics
    #pragma unroll
    for (int mf = 0; mf < 2; mf++) {
        #pragma unroll
        for (int half = 0; half < 2; half++) {
            float ps = 0.f, pq = 0.f;
            #pragma unroll
            for (int nf = 0; nf < 8; nf++) {
                float v0 = acc[mf][nf][half * 2 + 0];
                float v1 = acc[mf][nf][half * 2 + 1];
                ps += v0 + v1;
                pq += v0 * v0 + v1 * v1;
            }
            ps += __shfl_xor_sync(0xffffffffu, ps, 1);
            pq += __shfl_xor_sync(0xffffffffu, pq, 1);
            ps += __shfl_xor_sync(0xffffffffu, ps, 2);
            pq += __shfl_xor_sync(0xffffffffu, pq, 2);
            if (tg == 0) {
                int rl = wm * 32 + mf * 16 + half * 8 + g;
                ssum[rl * 4 + wn] = ps;
                ssq [rl * 4 + wn] = pq;
            }
        }
    }
    // stage lA[m] while stats land
    if (DOLORA) {
        int m = midx[brow / TOKPB];
        const float* Am = lA + (size_t)m * Hdim * RANKv;   // [256][8]
        #pragma unroll
        for (int hh = 0; hh < 8; hh++)
            laS[tid + hh * 256] = Am[tid + hh * 256];
    }
    __syncthreads();
    if (tid < 64) {
        float s = ssum[tid * 4] + ssum[tid * 4 + 1] + ssum[tid * 4 + 2] + ssum[tid * 4 + 3];
        float q = ssq [tid * 4] + ssq [tid * 4 + 1] + ssq [tid * 4 + 2] + ssq [tid * 4 + 3];
        float mu = s * (1.f / 256.f);
        float var = fmaxf(q * (1.f / 256.f) - mu * mu, 0.f);
        smu[tid] = mu;
        srs[tid] = rsqrtf(var + 1e-5f);
    }
    __syncthreads();

    // normalized write (+ lora partials)
    #pragma unroll
    for (int mf = 0; mf < 2; mf++) {
        int rl = wm * 32 + mf * 16 + g;
        float mu0 = smu[rl],     rs0 = srs[rl];
        float mu1 = smu[rl + 8], rs1 = srs[rl + 8];
        int r0 = brow + rl;
        float p0[RANKv], p1[RANKv];
        if (DOLORA) {
            #pragma unroll
            for (int r = 0; r < RANKv; r++) { p0[r] = 0.f; p1[r] = 0.f; }
        }
        #pragma unroll
        for (int nf = 0; nf < 8; nf++) {
            int col = wn * 64 + nf * 8 + tg * 2;
            float sc0 = lnS[col], sc1 = lnS[col + 1];
            float bi0 = lnB[col], bi1 = lnB[col + 1];
            float h0 = (acc[mf][nf][0] - mu0) * rs0 * sc0 + bi0;
            float h1 = (acc[mf][nf][1] - mu0) * rs0 * sc1 + bi1;
            float h2 = (acc[mf][nf][2] - mu1) * rs1 * sc0 + bi0;
            float h3 = (acc[mf][nf][3] - mu1) * rs1 * sc1 + bi1;
            if (DOLORA) {
                const float* l0 = laS + col * RANKv;
                const float* l1 = laS + (col + 1) * RANKv;
                #pragma unroll
                for (int r = 0; r < RANKv; r++) {
                    p0[r] += h0 * l0[r] + h1 * l1[r];
                    p1[r] += h2 * l0[r] + h3 * l1[r];
                }
            }
            if constexpr (sizeof(TO) == 2) {
                *(uint32_t*)((__nv_bfloat16*)Hout + (size_t)r0 * N + col)       = pack2bf(h0, h1);
                *(uint32_t*)((__nv_bfloat16*)Hout + (size_t)(r0 + 8) * N + col) = pack2bf(h2, h3);
            } else {
                *(float2*)((float*)Hout + (size_t)r0 * N + col)       = make_float2(h0, h1);
                *(float2*)((float*)Hout + (size_t)(r0 + 8) * N + col) = make_float2(h2, h3);
            }
        }
        if (DOLORA) {
            #pragma unroll
            for (int r = 0; r < RANKv; r++) {
                p0[r] += __shfl_xor_sync(0xffffffffu, p0[r], 1);
                p0[r] += __shfl_xor_sync(0xffffffffu, p0[r], 2);
                p1[r] += __shfl_xor_sync(0xffffffffu, p1[r], 1);
                p1[r] += __shfl_xor_sync(0xffffffffu, p1[r], 2);
            }
            if (tg == 0) {
                #pragma unroll
                for (int r = 0; r < RANKv; r++) {
                    red[(rl * RANKv + r) * 4 + wn]       = p0[r];
                    red[((rl + 8) * RANKv + r) * 4 + wn] = p1[r];
                }
            }
        }
    }

    if (DOLORA) {
        __syncthreads();
        #pragma unroll
        for (int hh = 0; hh < 2; hh++) {
            int i = tid + hh * 256;     // 512 (row, rank) pairs
            int row = i >> 3, r = i & 7;
            float s = red[i * 4] + red[i * 4 + 1] + red[i * 4 + 2] + red[i * 4 + 3];
            tmp[(size_t)(brow + row) * RANKv + r] = s;
        }
    }
}

// ---------------- merged weight transpose ----------------
__global__ void transpose_all_kernel(const float* __restrict__ Wqkv, const float* __restrict__ Wo,
                                     const float* __restrict__ W1,   const float* __restrict__ W2,
                                     __nv_bfloat16* __restrict__ wt)
{
    const size_t LSZ = 786432, OFF_WO = 196608, OFF_W1 = 262144, OFF_W2 = 524288;
    int bx = blockIdx.x, l = blockIdx.z;
    const float* src; __nv_bfloat16* dst; int K, N, tx, ty;
    if (bx < 192)      { int r = bx;       ty = r / 24, tx = r % 24; K = 256;  N = 768;
                         src = Wqkv + (size_t)l * 196608; dst = wt + l * LSZ; }
    else if (bx < 256) { int r = bx - 192; ty = r / 8,  tx = r % 8;  K = 256;  N = 256;
                         src = Wo + (size_t)l * 65536;   dst = wt + l * LSZ + OFF_WO; }
    else if (bx < 512) { int r = bx - 256; ty = r / 32, tx = r % 32; K = 256;  N = 1024;
                         src = W1 + (size_t)l * 262144;  dst = wt + l * LSZ + OFF_W1; }
    else               { int r = bx - 512; ty = r / 8,  tx = r % 8;  K = 1024; N = 256;
                         src = W2 + (size_t)l * 262144;  dst = wt + l * LSZ + OFF_W2; }

    __shared__ float t[32][33];
    int kb = ty * 32, nb = tx * 32;
    int x = threadIdx.x, y = threadIdx.y;
    #pragma unroll
    for (int i = 0; i < 32; i += 8)
        t[y + i][x] = src[(size_t)(kb + y + i) * N + nb + x];
    __syncthreads();
    #pragma unroll
    for (int i = 0; i < 32; i += 8)
        dst[(size_t)(nb + y + i) * K + kb + x] = __float2bfloat16(t[x][y + i]);
}

// ---------------- mask-format detection + category ----------------
__global__ void detect_cat_kernel(const unsigned char* __restrict__ sm,
                                  const unsigned char* __restrict__ hm,
                                  const unsigned char* __restrict__ gm,
                                  int* __restrict__ cat)
{
    __shared__ int offbyte, i32bad, f32bad, f32one;
    __shared__ int fmt_s;
    if (threadIdx.x == 0) { offbyte = 0; i32bad = 0; f32bad = 0; f32one = 0; }
    __syncthreads();
    const unsigned char* bufs[3] = {sm, hm, gm};
    for (int bi = 0; bi < 3; bi++) {
        const unsigned char* p = bufs[bi];
        for (int i = threadIdx.x; i < NTOK; i += blockDim.x)
            if ((i & 3) != 0 && p[i] != 0) atomicOr(&offbyte, 1);
        const int*   pi = (const int*)p;
        const float* pf = (const float*)p;
        for (int i = threadIdx.x; i < NTOK / 4; i += blockDim.x) {
            int iv = pi[i]; float fv = pf[i];
            if (iv != 0 && iv != 1)     atomicOr(&i32bad, 1);
            if (fv != 0.f && fv != 1.f) atomicOr(&f32bad, 1);
            if (fv == 1.f)              atomicOr(&f32one, 1);
        }
    }
    __syncthreads();
    if (threadIdx.x == 0) {
        int fmt;
        if (!offbyte && !i32bad)    fmt = 1;
        else if (!f32bad && f32one) fmt = 2;
        else                        fmt = 0;
        fmt_s = fmt;
    }
    __syncthreads();
    int fmt = fmt_s;
    for (int idx = threadIdx.x; idx < Bdim * Jm; idx += blockDim.x) {
        int b = idx / Jm, j = idx % Jm;
        int e = b * (Tdim * Jm) + j;
        bool sv, hv, gv;
        if (fmt == 0)      { sv = sm[e] != 0; hv = hm[e] != 0; gv = gm[e] != 0; }
        else if (fmt == 1) { sv = ((const int*)sm)[e] != 0; hv = ((const int*)hm)[e] != 0; gv = ((const int*)gm)[e] != 0; }
        else               { sv = ((const float*)sm)[e] != 0.f; hv = ((const float*)hm)[e] != 0.f; gv = ((const float*)gm)[e] != 0.f; }
        cat[idx] = sv ? 0 : (hv ? 1 : (gv ? 2 : 3));
    }
}

// ---------------- fused embed + LN1(layer0) + lora_tmp(layer0) ----------------
__global__ void embed_ln_tmp_kernel(const float* __restrict__ act,
                                    const int* __restrict__ m_idx, const int* __restrict__ cat,
                                    const float* __restrict__ Ws, const float* __restrict__ bs,
                                    const float* __restrict__ Wh, const float* __restrict__ bh,
                                    const float* __restrict__ Wg, const float* __restrict__ Wact,
                                    const float* __restrict__ pos,
                                    const float* __restrict__ lnS, const float* __restrict__ lnB,
                                    const float* __restrict__ lA,
                                    float* __restrict__ x, __nv_bfloat16* __restrict__ h,
                                    float* __restrict__ tmp)
{
    int warp = threadIdx.x >> 5, lane = threadIdx.x & 31;
    int token = blockIdx.x * 8 + warp;
    int j = token % Jm;
    int b = token / TOKPB;
    int m = m_idx[b];
    int ct = cat[b * Jm + j];
    float a = act[token];
    const float* posr = pos + ((size_t)m * Jm + j) * Hdim;
    const float* wgr  = Wg + (size_t)m * Hdim;

    float e[8];
    #pragma unroll
    for (int half = 0; half < 2; half++) {
        int c = (lane + half * 32) * 4;
        float4 r;
        if      (ct == 0) { float4 w = ld4(Ws, c), bb = ld4(bs, c);
                            r.x = a*w.x+bb.x; r.y = a*w.y+bb.y; r.z = a*w.z+bb.z; r.w = a*w.w+bb.w; }
        else if (ct == 1) { float4 w = ld4(Wh, c), bb = ld4(bh, c);
                            r.x = a*w.x+bb.x; r.y = a*w.y+bb.y; r.z = a*w.z+bb.z; r.w = a*w.w+bb.w; }
        else if (ct == 2) { float4 w = ld4(wgr, c);
                            r.x = a*w.x; r.y = a*w.y; r.z = a*w.z; r.w = a*w.w; }
        else              { r = make_float4(0.f, 0.f, 0.f, 0.f); }
        if (ct != 3) { float4 wa = ld4(Wact, c); r.x += wa.x; r.y += wa.y; r.z += wa.z; r.w += wa.w; }
        float4 p = ld4(posr, c);
        r.x += p.x; r.y += p.y; r.z += p.z; r.w += p.w;
        e[half*4+0] = r.x; e[half*4+1] = r.y; e[half*4+2] = r.z; e[half*4+3] = r.w;
        *(float4*)(x + (size_t)token * Hdim + c) = r;
    }

    float s = 0.f;
    #pragma unroll
    for (int q = 0; q < 8; q++) s += e[q];
    #pragma unroll
    for (int o = 16; o > 0; o >>= 1) s += __shfl_xor_sync(0xffffffffu, s, o);
    float mu = s * (1.f / Hdim);
    float v = 0.f;
    #pragma unroll
    for (int q = 0; q < 8; q++) { e[q] -= mu; v += e[q] * e[q]; }
    #pragma unroll
    for (int o = 16; o > 0; o >>= 1) v += __shfl_xor_sync(0xffffffffu, v, o);
    float rs = rsqrtf(v * (1.f / Hdim) + 1e-5f);

    float hv[8];
    #pragma unroll
    for (int half = 0; half < 2; half++) {
        int c = (lane + half * 32) * 4;
        float4 sc4 = ld4(lnS, c), bi4 = ld4(lnB, c);
        hv[half*4+0] = e[half*4+0] * rs * sc4.x + bi4.x;
        hv[half*4+1] = e[half*4+1] * rs * sc4.y + bi4.y;
        hv[half*4+2] = e[half*4+2] * rs * sc4.z + bi4.z;
        hv[half*4+3] = e[half*4+3] * rs * sc4.w + bi4.w;
        *(uint2*)(h + (size_t)token * Hdim + c) =
            make_uint2(pack2bf(hv[half*4+0], hv[half*4+1]), pack2bf(hv[half*4+2], hv[half*4+3]));
    }

    const float* Am = lA + (size_t)m * Hdim * RANKv;
    float t0=0,t1=0,t2=0,t3=0,t4=0,t5=0,t6=0,t7=0;
    #pragma unroll
    for (int q = 0; q < 8; q++) {
        int c = (lane + (q >> 2) * 32) * 4 + (q & 3);
        float4 a0 = ld4(Am + (size_t)c * RANKv, 0);
        float4 a1 = ld4(Am + (size_t)c * RANKv, 4);
        float hq = hv[q];
        t0 += hq * a0.x; t1 += hq * a0.y; t2 += hq * a0.z; t3 += hq * a0.w;
        t4 += hq * a1.x; t5 += hq * a1.y; t6 += hq * a1.z; t7 += hq * a1.w;
    }
    #pragma unroll
    for (int o = 16; o > 0; o >>= 1) {
        t0 += __shfl_xor_sync(0xffffffffu, t0, o);
        t1 += __shfl_xor_sync(0xffffffffu, t1, o);
        t2 += __shfl_xor_sync(0xffffffffu, t2, o);
        t3 += __shfl_xor_sync(0xffffffffu, t3, o);
        t4 += __shfl_xor_sync(0xffffffffu, t4, o);
        t5 += __shfl_xor_sync(0xffffffffu, t5, o);
        t6 += __shfl_xor_sync(0xffffffffu, t6, o);
        t7 += __shfl_xor_sync(0xffffffffu, t7, o);
    }
    if (lane == 0) {
        float* tp = tmp + (size_t)token * RANKv;
        *(float4*)tp       = make_float4(t0, t1, t2, t3);
        *(float4*)(tp + 4) = make_float4(t4, t5, t6, t7);
    }
}

// ---------------- attention: one CTA per (sequence, head); vectorized loads ----------------
#define APAD (DH + 2)

__global__ void attn_kernel(const __nv_bfloat16* __restrict__ qkv, __nv_bfloat16* __restrict__ o,
                            const int* __restrict__ m_idx)
{
    __shared__ float qs[Jm][APAD];
    __shared__ float ks[Jm][APAD];
    __shared__ float vs[Jm][APAD];
    __shared__ float sc[Jm][Jm + 1];
    int n = blockIdx.x, head = blockIdx.y;
    int b = n >> 7;
    int nj = c_nj[m_idx[b]];
    const float scale = 0.17677669529663687f;

    const __nv_bfloat16* base = qkv + (size_t)n * Jm * H3 + head * DH;
    #pragma unroll
    for (int it = 0; it < 9; it++) {
        int idx = threadIdx.x + it * 128;
        int seg = idx / 384;
        int rem = idx - seg * 384;
        int j = rem >> 4, c = (rem & 15) * 2;
        __nv_bfloat162 hv2 = *(const __nv_bfloat162*)(base + (size_t)j * H3 + seg * Hdim + c);
        float2 f = __bfloat1622float2(hv2);
        if (seg == 0)      { qs[j][c] = f.x * scale; qs[j][c + 1] = f.y * scale; }
        else if (seg == 1) { ks[j][c] = f.x;         ks[j][c + 1] = f.y; }
        else               { vs[j][c] = f.x;         vs[j][c + 1] = f.y; }
    }
    __syncthreads();

    for (int idx = threadIdx.x; idx < Jm * Jm; idx += blockDim.x) {
        int i = idx / Jm, j = idx % Jm;
        bool ok = (i < nj && j < nj) || (i == j);
        float s = -3.402823466e38f;
        if (ok) {
            s = 0.f;
            #pragma unroll
            for (int d = 0; d < DH; d++) s += qs[i][d] * ks[j][d];
        }
        sc[i][j] = s;
    }
    __syncthreads();
    if (threadIdx.x < Jm) {
        int i = threadIdx.x;
        float mx = -3.402823466e38f;
        #pragma unroll
        for (int j = 0; j < Jm; j++) mx = fmaxf(mx, sc[i][j]);
        float e[Jm]; float sum = 0.f;
        #pragma unroll
        for (int j = 0; j < Jm; j++) { e[j] = expf(sc[i][j] - mx); sum += e[j]; }
        float inv = 1.f / sum;
        #pragma unroll
        for (int j = 0; j < Jm; j++) sc[i][j] = e[j] * inv;
    }
    __syncthreads();
    for (int idx = threadIdx.x; idx < Jm * DH; idx += blockDim.x) {
        int i = idx >> 5, d = idx & 31;
        float a0 = 0.f;
        #pragma unroll
        for (int j = 0; j < Jm; j++) a0 += sc[i][j] * vs[j][d];
        o[((size_t)(n * Jm + i)) * Hdim + head * DH + d] = __float2bfloat16(a0);
    }
}

// ---------------- launcher ----------------
extern "C" void kernel_launch(void* const* d_in, const int* in_sizes, int n_in,
                              void* d_out, int out_size)
{
    (void)in_sizes; (void)n_in; (void)out_size;
    const float* act   = (const float*)d_in[0];
    const unsigned char* smk = (const unsigned char*)d_in[1];
    const unsigned char* hmk = (const unsigned char*)d_in[2];
    const unsigned char* gmk = (const unsigned char*)d_in[3];
    const int*   m_idx = (const int*)d_in[6];
    const float* Ws    = (const float*)d_in[7];
    const float* bs    = (const float*)d_in[8];
    const float* Wh    = (const float*)d_in[9];
    const float* bh    = (const float*)d_in[10];
    const float* Wg    = (const float*)d_in[11];
    const float* Wact  = (const float*)d_in[12];
    const float* pos   = (const float*)d_in[13];
    const float* ln1_s = (const float*)d_in[14];
    const float* ln1_b = (const float*)d_in[15];
    const float* Wqkv  = (const float*)d_in[16];
    const float* bqkv  = (const float*)d_in[17];
    const float* loraA = (const float*)d_in[18];
    const float* loraB = (const float*)d_in[19];
    const float* Wo    = (const float*)d_in[20];
    const float* bo    = (const float*)d_in[21];
    const float* ln2_s = (const float*)d_in[22];
    const float* ln2_b = (const float*)d_in[23];
    const float* W1    = (const float*)d_in[24];
    const float* b1    = (const float*)d_in[25];
    const float* W2    = (const float*)d_in[26];
    const float* b2    = (const float*)d_in[27];
    const float* g1    = (const float*)d_in[28];
    const float* g2    = (const float*)d_in[29];
    const float* lnf_s = (const float*)d_in[30];
    const float* lnf_b = (const float*)d_in[31];
    float* out = (float*)d_out;

    float *x, *tmp; __nv_bfloat16 *h, *qkv, *ob, *midb, *wt; int *cat;
    cudaGetSymbolAddress((void**)&x,    g_x);
    cudaGetSymbolAddress((void**)&h,    g_h);
    cudaGetSymbolAddress((void**)&qkv,  g_qkv);
    cudaGetSymbolAddress((void**)&ob,   g_o);
    cudaGetSymbolAddress((void**)&midb, g_midb);
    cudaGetSymbolAddress((void**)&tmp,  g_tmp);
    cudaGetSymbolAddress((void**)&wt,   g_wt);
    cudaGetSymbolAddress((void**)&cat,  g_cat);

    cudaFuncSetAttribute((const void*)hmma_gemm_kernel<1, 256>,               cudaFuncAttributeMaxDynamicSharedMemorySize, GSMEM);
    cudaFuncSetAttribute((const void*)hmma_gemm_kernel<3, 256>,               cudaFuncAttributeMaxDynamicSharedMemorySize, GSMEM);
    cudaFuncSetAttribute((const void*)hmma_ln_kernel<__nv_bfloat16, 256, 0>,  cudaFuncAttributeMaxDynamicSharedMemorySize, GSMEM2);
    cudaFuncSetAttribute((const void*)hmma_ln_kernel<__nv_bfloat16, 1024, 1>, cudaFuncAttributeMaxDynamicSharedMemorySize, GSMEM2);
    cudaFuncSetAttribute((const void*)hmma_ln_kernel<float, 1024, 0>,         cudaFuncAttributeMaxDynamicSharedMemorySize, GSMEM2);

    const size_t OFF_QKV = 0, OFF_WO = 196608, OFF_W1 = 262144, OFF_W2 = 524288, LSZ = 786432;

    transpose_all_kernel<<<dim3(768, 1, Lnum), dim3(32, 8)>>>(Wqkv, Wo, W1, W2, wt);
    detect_cat_kernel<<<1, 256>>>(smk, hmk, gmk, cat);
    embed_ln_tmp_kernel<<<NTOK / 8, 256>>>(act, m_idx, cat, Ws, bs, Wh, bh, Wg, Wact, pos,
                                           ln1_s, ln1_b, loraA, x, h, tmp);

    for (int l = 0; l < Lnum; l++) {
        // launch 4 on first iter: qkv GEMM (ncu target)
        hmma_gemm_kernel<3, 256><<<dim3(H3 / 128, NTOK / 128), 256, GSMEM>>>(
            h, wt + l * LSZ + OFF_QKV, qkv, bqkv + l * H3,
            tmp, loraB + (size_t)l * Mnum * RANKv * H3, m_idx, H3);
        attn_kernel<<<dim3(NSEQ, HEADS), 128>>>(qkv, ob, m_idx);
        hmma_ln_kernel<__nv_bfloat16, 256, 0><<<dim3(1, NTOK / 64), 256, GSMEM2>>>(
            ob, wt + l * LSZ + OFF_WO, x, bo + l * Hdim, g1 + l * Hdim,
            ln2_s + l * Hdim, ln2_b + l * Hdim, h, nullptr, nullptr, nullptr);
        hmma_gemm_kernel<1, 256><<<dim3(H4 / 128, NTOK / 128), 256, GSMEM>>>(
            h, wt + l * LSZ + OFF_W1, midb, b1 + l * H4,
            nullptr, nullptr, nullptr, H4);
        if (l < Lnum - 1) {
            // W2 + LN1(l+1) + fused lora_tmp for layer l+1
            hmma_ln_kernel<__nv_bfloat16, 1024, 1><<<dim3(1, NTOK / 64), 256, GSMEM2>>>(
                midb, wt + l * LSZ + OFF_W2, x, b2 + l * Hdim, g2 + l * Hdim,
                ln1_s + (l + 1) * Hdim, ln1_b + (l + 1) * Hdim, h,
                loraA + (size_t)(l + 1) * Mnum * Hdim * RANKv, m_idx, tmp);
        } else {
            hmma_ln_kernel<float, 1024, 0><<<dim3(1, NTOK / 64), 256, GSMEM2>>>(
                midb, wt + l * LSZ + OFF_W2, x, b2 + l * Hdim, g2 + l * Hdim,
                lnf_s, lnf_b, out, nullptr, nullptr, nullptr);
        }
    }
}

// round 14
// speedup vs baseline: 1.5059x; 1.5059x over previous
#include <cuda_runtime.h>
#include <cuda_bf16.h>
#include <math.h>
#include <stdint.h>

// ---------------- problem constants ----------------
#define NTOK  49152
#define NSEQ  2048
#define Bdim  16
#define Tdim  128
#define Jm    24
#define Hdim  256
#define H3    768
#define H4    1024
#define Lnum  4
#define Mnum  12
#define RANKv 8
#define HEADS 8
#define DH    32
#define TOKPB 3072

__constant__ int c_nj[Mnum] = {8,10,12,14,16,18,20,22,24,9,13,17};

// ---------------- scratch ----------------
__device__ float         g_x   [(size_t)NTOK * Hdim];
__device__ __nv_bfloat16 g_h   [(size_t)NTOK * Hdim];
__device__ __nv_bfloat16 g_qkv [(size_t)NTOK * H3 ];
__device__ __nv_bfloat16 g_o   [(size_t)NTOK * Hdim];
__device__ __nv_bfloat16 g_midb[(size_t)NTOK * H4 ];
__device__ float         g_tmp [(size_t)NTOK * RANKv];
__device__ __nv_bfloat16 g_wt  [(size_t)Lnum * 786432];
__device__ int           g_cat [Bdim * Jm];

// ---------------- helpers ----------------
__device__ __forceinline__ uint32_t smem_u32(const void* p) {
    uint32_t a;
    asm("{ .reg .u64 t; cvta.to.shared.u64 t, %1; cvt.u32.u64 %0, t; }" : "=r"(a) : "l"(p));
    return a;
}
__device__ __forceinline__ void cp16(uint32_t dst, const void* src) {
    asm volatile("cp.async.cg.shared.global [%0], [%1], 16;" :: "r"(dst), "l"(src));
}
__device__ __forceinline__ void cp_commit() { asm volatile("cp.async.commit_group;"); }
__device__ __forceinline__ void ldm_x4(uint32_t& r0, uint32_t& r1, uint32_t& r2, uint32_t& r3, uint32_t a) {
    asm volatile("ldmatrix.sync.aligned.m8n8.x4.shared.b16 {%0,%1,%2,%3}, [%4];"
                 : "=r"(r0), "=r"(r1), "=r"(r2), "=r"(r3) : "r"(a));
}
__device__ __forceinline__ void mma16816(float* c, const uint32_t* a, const uint32_t* b) {
    asm volatile("mma.sync.aligned.m16n8k16.row.col.f32.bf16.bf16.f32 "
                 "{%0,%1,%2,%3},{%4,%5,%6,%7},{%8,%9},{%0,%1,%2,%3};"
                 : "+f"(c[0]), "+f"(c[1]), "+f"(c[2]), "+f"(c[3])
                 : "r"(a[0]), "r"(a[1]), "r"(a[2]), "r"(a[3]), "r"(b[0]), "r"(b[1]));
}
__device__ __forceinline__ uint32_t pack2bf(float x, float y) {
    __nv_bfloat162 h = __floats2bfloat162_rn(x, y);
    return *reinterpret_cast<uint32_t*>(&h);
}
__device__ __forceinline__ float gelu_tanh(float x) {
    float x3 = x * x * x;
    return 0.5f * x * (1.f + tanhf(0.7978845608028654f * (x + 0.044715f * x3)));
}
__device__ __forceinline__ float4 ld4(const float* p, int c) { return *(const float4*)(p + c); }

// ================= kernel 1: 128x128 HMMA GEMM, compile-time K (R11 proven) =================
#define TILE2  16384
#define NSTG   3
#define GSMEM  (NSTG * 2 * TILE2)    // 98304

template<int EPI, int KT>
__global__ void __launch_bounds__(256, 2)
hmma_gemm_kernel(const __nv_bfloat16* __restrict__ A, const __nv_bfloat16* __restrict__ Bt,
                 __nv_bfloat16* __restrict__ Cb,
                 const float* __restrict__ bias,
                 const float* __restrict__ ltmp, const float* __restrict__ lB,
                 const int* __restrict__ midx,
                 int N)
{
    extern __shared__ char dynsm[];
    constexpr int NCH = KT >> 6;

    int tid = threadIdx.x, lane = tid & 31, wid = tid >> 5;
    int wm = wid & 1, wn = wid >> 1;
    int brow = blockIdx.y * 128, bcol = blockIdx.x * 128;

    float acc[4][4][4];
    #pragma unroll
    for (int i = 0; i < 4; i++)
        #pragma unroll
        for (int j = 0; j < 4; j++)
            #pragma unroll
            for (int q = 0; q < 4; q++) acc[i][j][q] = 0.f;

    int lrow = tid >> 3, lcc = tid & 7;
    uint32_t soff0 = (uint32_t)(lrow * 128 + ((lcc ^ (lrow & 7)) * 16));
    const __nv_bfloat16* Ap0 = A + (size_t)(brow + lrow) * KT + lcc * 8;
    const __nv_bfloat16* Bp0 = Bt + (size_t)(bcol + lrow) * KT + lcc * 8;
    uint32_t smbase = smem_u32(dynsm);

    auto load_tiles = [&](int ch, int stage) {
        uint32_t da = smbase + (uint32_t)((stage * 2 + 0) * TILE2) + soff0;
        uint32_t db = smbase + (uint32_t)((stage * 2 + 1) * TILE2) + soff0;
        const __nv_bfloat16* Ah = Ap0 + ch * 64;
        const __nv_bfloat16* Bh = Bp0 + ch * 64;
        #pragma unroll
        for (int hh = 0; hh < 4; hh++) {
            cp16(da + hh * 4096, Ah + hh * 32 * KT);
            cp16(db + hh * 4096, Bh + hh * 32 * KT);
        }
        cp_commit();
    };

    int rsel = lane & 15, ksel = lane >> 4;
    uint32_t abase[4], bbase[2];
    #pragma unroll
    for (int mf = 0; mf < 4; mf++) {
        int ar = wm * 64 + mf * 16 + rsel;
        abase[mf] = (uint32_t)(ar * 128 + (ar & 7) * 16);
    }
    #pragma unroll
    for (int nf2 = 0; nf2 < 2; nf2++) {
        int br = wn * 32 + nf2 * 16 + rsel;
        bbase[nf2] = (uint32_t)(br * 128 + (br & 7) * 16);
    }

    load_tiles(0, 0);
    load_tiles(1, 1);

    #pragma unroll
    for (int ch = 0; ch < NCH; ch++) {
        asm volatile("cp.async.wait_group 1;");
        __syncthreads();

        uint32_t sa = smbase + (uint32_t)(((ch % NSTG) * 2 + 0) * TILE2);
        uint32_t sb = smbase + (uint32_t)(((ch % NSTG) * 2 + 1) * TILE2);

        #pragma unroll
        for (int ks = 0; ks < 4; ks++) {
            uint32_t cx = (uint32_t)((ks * 2 + ksel) * 16);
            uint32_t a[4][4];
            #pragma unroll
            for (int mf = 0; mf < 4; mf++)
                ldm_x4(a[mf][0], a[mf][1], a[mf][2], a[mf][3], sa + (abase[mf] ^ cx));
            uint32_t b[4][2];
            #pragma unroll
            for (int nf2 = 0; nf2 < 2; nf2++) {
                uint32_t r0, r1, r2, r3;
                ldm_x4(r0, r1, r2, r3, sb + (bbase[nf2] ^ cx));
                b[nf2 * 2 + 0][0] = r0; b[nf2 * 2 + 0][1] = r2;
                b[nf2 * 2 + 1][0] = r1; b[nf2 * 2 + 1][1] = r3;
            }
            #pragma unroll
            for (int mf = 0; mf < 4; mf++)
                #pragma unroll
                for (int nf = 0; nf < 4; nf++)
                    mma16816(acc[mf][nf], a[mf], b[nf]);
        }

        if (ch + 2 < NCH) load_tiles(ch + 2, (ch + 2) % NSTG);
        else              cp_commit();
    }

    float* lb_s  = (float*)dynsm;
    float* tmp_s = (float*)(dynsm + 4096);
    if (EPI == 3) {
        __syncthreads();
        int m = midx[brow / TOKPB];
        #pragma unroll
        for (int hh = 0; hh < 4; hh++) {
            int i = tid + hh * 256;
            int q = i >> 7, c = i & 127;
            lb_s[q * 128 + c] = lB[((size_t)m * RANKv + q) * N + bcol + c];
            int r = i >> 3, q2 = i & 7;
            tmp_s[r * 9 + q2] = ltmp[(size_t)(brow + r) * RANKv + q2];
        }
        __syncthreads();
    }

    int g = lane >> 2, tg = lane & 3;
    #pragma unroll
    for (int mf = 0; mf < 4; mf++) {
        int rl = wm * 64 + mf * 16 + g;
        int r0 = brow + rl;
        #pragma unroll
        for (int nf = 0; nf < 4; nf++) {
            int cl  = wn * 32 + nf * 8 + tg * 2;
            int col = bcol + cl;
            float b0 = bias[col], b1 = bias[col + 1];
            float v0 = acc[mf][nf][0] + b0, v1 = acc[mf][nf][1] + b1;
            float v2 = acc[mf][nf][2] + b0, v3 = acc[mf][nf][3] + b1;
            if (EPI == 1) {
                *(uint32_t*)(Cb + (size_t)r0 * N + col)       = pack2bf(gelu_tanh(v0), gelu_tanh(v1));
                *(uint32_t*)(Cb + (size_t)(r0 + 8) * N + col) = pack2bf(gelu_tanh(v2), gelu_tanh(v3));
            } else {
                float a00 = 0.f, a01 = 0.f, a10 = 0.f, a11 = 0.f;
                #pragma unroll
                for (int q = 0; q < 8; q++) {
                    float w0 = lb_s[q * 128 + cl], w1 = lb_s[q * 128 + cl + 1];
                    float u0 = tmp_s[rl * 9 + q], u1 = tmp_s[(rl + 8) * 9 + q];
                    a00 += u0 * w0; a01 += u0 * w1;
                    a10 += u1 * w0; a11 += u1 * w1;
                }
                *(uint32_t*)(Cb + (size_t)r0 * N + col)       = pack2bf(v0 + a00, v1 + a01);
                *(uint32_t*)(Cb + (size_t)(r0 + 8) * N + col) = pack2bf(v2 + a10, v3 + a11);
            }
        }
    }
}

// ================= kernel 2: 64x256 HMMA GEMM + residual + fused LN (+ fused lora_tmp) ===========
#define TA64   8192
#define TB256  32768
#define STG64  (TA64 + TB256)        // 40960
#define GSMEM2 (2 * STG64)           // 81920

template<typename TO, int KT, int DOLORA>
__global__ void __launch_bounds__(256, 2)
hmma_ln_kernel(const __nv_bfloat16* __restrict__ A, const __nv_bfloat16* __restrict__ Bt,
               float* __restrict__ C,
               const float* __restrict__ bias, const float* __restrict__ gsc,
               const float* __restrict__ lnS, const float* __restrict__ lnB,
               TO* __restrict__ Hout,
               const float* __restrict__ lA, const int* __restrict__ midx,
               float* __restrict__ tmp)
{
    extern __shared__ char dynsm[];
    const int N = 256;
    constexpr int NCH = KT >> 6;

    int tid = threadIdx.x, lane = tid & 31, wid = tid >> 5;
    int wm = wid & 1, wn = wid >> 1;
    int brow = blockIdx.y * 64;

    float acc[2][8][4];
    #pragma unroll
    for (int i = 0; i < 2; i++)
        #pragma unroll
        for (int j = 0; j < 8; j++)
            #pragma unroll
            for (int q = 0; q < 4; q++) acc[i][j][q] = 0.f;

    int lrow = tid >> 3, lcc = tid & 7;
    uint32_t soff0 = (uint32_t)(lrow * 128 + ((lcc ^ (lrow & 7)) * 16));
    const __nv_bfloat16* Ap0 = A + (size_t)(brow + lrow) * KT + lcc * 8;
    const __nv_bfloat16* Bp0 = Bt + (size_t)lrow * KT + lcc * 8;
    uint32_t smbase = smem_u32(dynsm);

    auto load_tiles = [&](int ch, int stage) {
        uint32_t da = smbase + (uint32_t)(stage * STG64) + soff0;
        uint32_t db = da + TA64;
        const __nv_bfloat16* Ah = Ap0 + ch * 64;
        const __nv_bfloat16* Bh = Bp0 + ch * 64;
        #pragma unroll
        for (int hh = 0; hh < 2; hh++)
            cp16(da + hh * 4096, Ah + hh * 32 * KT);
        #pragma unroll
        for (int hh = 0; hh < 8; hh++)
            cp16(db + hh * 4096, Bh + hh * 32 * KT);
        cp_commit();
    };

    int rsel = lane & 15, ksel = lane >> 4;
    uint32_t abase[2], bbase[4];
    #pragma unroll
    for (int mf = 0; mf < 2; mf++) {
        int ar = wm * 32 + mf * 16 + rsel;
        abase[mf] = (uint32_t)(ar * 128 + (ar & 7) * 16);
    }
    #pragma unroll
    for (int nf2 = 0; nf2 < 4; nf2++) {
        int br = wn * 64 + nf2 * 16 + rsel;
        bbase[nf2] = (uint32_t)(br * 128 + (br & 7) * 16);
    }

    load_tiles(0, 0);

    for (int ch = 0; ch < NCH; ch++) {
        if (ch + 1 < NCH) {
            load_tiles(ch + 1, (ch + 1) & 1);
            asm volatile("cp.async.wait_group 1;");
        } else {
            asm volatile("cp.async.wait_group 0;");
        }
        __syncthreads();

        uint32_t sa = smbase + (uint32_t)((ch & 1) * STG64);
        uint32_t sb = sa + TA64;

        #pragma unroll
        for (int ks = 0; ks < 4; ks++) {
            uint32_t cx = (uint32_t)((ks * 2 + ksel) * 16);
            uint32_t a[2][4];
            #pragma unroll
            for (int mf = 0; mf < 2; mf++)
                ldm_x4(a[mf][0], a[mf][1], a[mf][2], a[mf][3], sa + (abase[mf] ^ cx));
            uint32_t b[8][2];
            #pragma unroll
            for (int nf2 = 0; nf2 < 4; nf2++) {
                uint32_t r0, r1, r2, r3;
                ldm_x4(r0, r1, r2, r3, sb + (bbase[nf2] ^ cx));
                b[nf2 * 2 + 0][0] = r0; b[nf2 * 2 + 0][1] = r2;
                b[nf2 * 2 + 1][0] = r1; b[nf2 * 2 + 1][1] = r3;
            }
            #pragma unroll
            for (int mf = 0; mf < 2; mf++)
                #pragma unroll
                for (int nf = 0; nf < 8; nf++)
                    mma16816(acc[mf][nf], a[mf], b[nf]);
        }
        __syncthreads();
    }

    int g = lane >> 2, tg = lane & 3;

    // residual rmw; updated x stays in acc
    #pragma unroll
    for (int mf = 0; mf < 2; mf++) {
        int r0 = brow + wm * 32 + mf * 16 + g;
        #pragma unroll
        for (int nf = 0; nf < 8; nf++) {
            int col = wn * 64 + nf * 8 + tg * 2;
            float b0 = bias[col], b1 = bias[col + 1];
            float s0 = gsc[col],  s1 = gsc[col + 1];
            float2 o0 = *(float2*)(C + (size_t)r0 * N + col);
            float2 o1 = *(float2*)(C + (size_t)(r0 + 8) * N + col);
            o0.x += s0 * (acc[mf][nf][0] + b0); o0.y += s1 * (acc[mf][nf][1] + b1);
            o1.x += s0 * (acc[mf][nf][2] + b0); o1.y += s1 * (acc[mf][nf][3] + b1);
            *(float2*)(C + (size_t)r0 * N + col)       = o0;
            *(float2*)(C + (size_t)(r0 + 8) * N + col) = o1;
            acc[mf][nf][0] = o0.x; acc[mf][nf][1] = o0.y;
            acc[mf][nf][2] = o1.x; acc[mf][nf][3] = o1.y;
        }
    }

    float* ssum = (float*)dynsm;         // [64][4]
    float* ssq  = ssum + 256;            // [64][4]
    float* smu  = ssq + 256;             // [64]
    float* srs  = smu + 64;              // [64]
    float* laS  = srs + 64;              // [256][8]  (DOLORA)
    float* red  = laS + 2048;            // [64][8][4] (DOLORA)
    __syncthreads();

    #pragma unroll
    for (int mf = 0; mf < 2; mf++) {
        #pragma unroll
        for (int half = 0; half < 2; half++) {
            float ps = 0.f, pq = 0.f;
            #pragma unroll
            for (int nf = 0; nf < 8; nf++) {
                float v0 = acc[mf][nf][half * 2 + 0];
                float v1 = acc[mf][nf][half * 2 + 1];
                ps += v0 + v1;
                pq += v0 * v0 + v1 * v1;
            }
            ps += __shfl_xor_sync(0xffffffffu, ps, 1);
            pq += __shfl_xor_sync(0xffffffffu, pq, 1);
            ps += __shfl_xor_sync(0xffffffffu, ps, 2);
            pq += __shfl_xor_sync(0xffffffffu, pq, 2);
            if (tg == 0) {
                int rl = wm * 32 + mf * 16 + half * 8 + g;
                ssum[rl * 4 + wn] = ps;
                ssq [rl * 4 + wn] = pq;
            }
        }
    }
    if (DOLORA) {
        int m = midx[brow / TOKPB];
        const float4* Am4 = (const float4*)(lA + (size_t)m * Hdim * RANKv);  // 512 float4
        float4* laS4 = (float4*)laS;
        laS4[tid]       = Am4[tid];
        laS4[tid + 256] = Am4[tid + 256];
    }
    __syncthreads();
    if (tid < 64) {
        float s = ssum[tid * 4] + ssum[tid * 4 + 1] + ssum[tid * 4 + 2] + ssum[tid * 4 + 3];
        float q = ssq [tid * 4] + ssq [tid * 4 + 1] + ssq [tid * 4 + 2] + ssq [tid * 4 + 3];
        float mu = s * (1.f / 256.f);
        float var = fmaxf(q * (1.f / 256.f) - mu * mu, 0.f);
        smu[tid] = mu;
        srs[tid] = rsqrtf(var + 1e-5f);
    }
    __syncthreads();

    #pragma unroll
    for (int mf = 0; mf < 2; mf++) {
        int rl = wm * 32 + mf * 16 + g;
        float mu0 = smu[rl],     rs0 = srs[rl];
        float mu1 = smu[rl + 8], rs1 = srs[rl + 8];
        int r0 = brow + rl;
        float p0[RANKv], p1[RANKv];
        if (DOLORA) {
            #pragma unroll
            for (int r = 0; r < RANKv; r++) { p0[r] = 0.f; p1[r] = 0.f; }
        }
        #pragma unroll
        for (int nf = 0; nf < 8; nf++) {
            int col = wn * 64 + nf * 8 + tg * 2;
            float sc0 = lnS[col], sc1 = lnS[col + 1];
            float bi0 = lnB[col], bi1 = lnB[col + 1];
            float h0 = (acc[mf][nf][0] - mu0) * rs0 * sc0 + bi0;
            float h1 = (acc[mf][nf][1] - mu0) * rs0 * sc1 + bi1;
            float h2 = (acc[mf][nf][2] - mu1) * rs1 * sc0 + bi0;
            float h3 = (acc[mf][nf][3] - mu1) * rs1 * sc1 + bi1;
            if (DOLORA) {
                const float* l0 = laS + col * RANKv;
                const float* l1 = laS + (col + 1) * RANKv;
                #pragma unroll
                for (int r = 0; r < RANKv; r++) {
                    p0[r] += h0 * l0[r] + h1 * l1[r];
                    p1[r] += h2 * l0[r] + h3 * l1[r];
                }
            }
            if constexpr (sizeof(TO) == 2) {
                *(uint32_t*)((__nv_bfloat16*)Hout + (size_t)r0 * N + col)       = pack2bf(h0, h1);
                *(uint32_t*)((__nv_bfloat16*)Hout + (size_t)(r0 + 8) * N + col) = pack2bf(h2, h3);
            } else {
                *(float2*)((float*)Hout + (size_t)r0 * N + col)       = make_float2(h0, h1);
                *(float2*)((float*)Hout + (size_t)(r0 + 8) * N + col) = make_float2(h2, h3);
            }
        }
        if (DOLORA) {
            #pragma unroll
            for (int r = 0; r < RANKv; r++) {
                p0[r] += __shfl_xor_sync(0xffffffffu, p0[r], 1);
                p0[r] += __shfl_xor_sync(0xffffffffu, p0[r], 2);
                p1[r] += __shfl_xor_sync(0xffffffffu, p1[r], 1);
                p1[r] += __shfl_xor_sync(0xffffffffu, p1[r], 2);
            }
            if (tg == 0) {
                #pragma unroll
                for (int r = 0; r < RANKv; r++) {
                    red[(rl * RANKv + r) * 4 + wn]       = p0[r];
                    red[((rl + 8) * RANKv + r) * 4 + wn] = p1[r];
                }
            }
        }
    }

    if (DOLORA) {
        __syncthreads();
        #pragma unroll
        for (int hh = 0; hh < 2; hh++) {
            int i = tid + hh * 256;
            int row = i >> 3, r = i & 7;
            float4 v = *(float4*)(red + i * 4);
            tmp[(size_t)(brow + row) * RANKv + r] = v.x + v.y + v.z + v.w;
        }
    }
}

// ---------------- merged weight transpose ----------------
__global__ void transpose_all_kernel(const float* __restrict__ Wqkv, const float* __restrict__ Wo,
                                     const float* __restrict__ W1,   const float* __restrict__ W2,
                                     __nv_bfloat16* __restrict__ wt)
{
    const size_t LSZ = 786432, OFF_WO = 196608, OFF_W1 = 262144, OFF_W2 = 524288;
    int bx = blockIdx.x, l = blockIdx.z;
    const float* src; __nv_bfloat16* dst; int K, N, tx, ty;
    if (bx < 192)      { int r = bx;       ty = r / 24, tx = r % 24; K = 256;  N = 768;
                         src = Wqkv + (size_t)l * 196608; dst = wt + l * LSZ; }
    else if (bx < 256) { int r = bx - 192; ty = r / 8,  tx = r % 8;  K = 256;  N = 256;
                         src = Wo + (size_t)l * 65536;   dst = wt + l * LSZ + OFF_WO; }
    else if (bx < 512) { int r = bx - 256; ty = r / 32, tx = r % 32; K = 256;  N = 1024;
                         src = W1 + (size_t)l * 262144;  dst = wt + l * LSZ + OFF_W1; }
    else               { int r = bx - 512; ty = r / 8,  tx = r % 8;  K = 1024; N = 256;
                         src = W2 + (size_t)l * 262144;  dst = wt + l * LSZ + OFF_W2; }

    __shared__ float t[32][33];
    int kb = ty * 32, nb = tx * 32;
    int x = threadIdx.x, y = threadIdx.y;
    #pragma unroll
    for (int i = 0; i < 32; i += 8)
        t[y + i][x] = src[(size_t)(kb + y + i) * N + nb + x];
    __syncthreads();
    #pragma unroll
    for (int i = 0; i < 32; i += 8)
        dst[(size_t)(nb + y + i) * K + kb + x] = __float2bfloat16(t[x][y + i]);
}

// ---------------- mask-format detection + category ----------------
__global__ void detect_cat_kernel(const unsigned char* __restrict__ sm,
                                  const unsigned char* __restrict__ hm,
                                  const unsigned char* __restrict__ gm,
                                  int* __restrict__ cat)
{
    __shared__ int offbyte, i32bad, f32bad, f32one;
    __shared__ int fmt_s;
    if (threadIdx.x == 0) { offbyte = 0; i32bad = 0; f32bad = 0; f32one = 0; }
    __syncthreads();
    const unsigned char* bufs[3] = {sm, hm, gm};
    for (int bi = 0; bi < 3; bi++) {
        const unsigned char* p = bufs[bi];
        for (int i = threadIdx.x; i < NTOK; i += blockDim.x)
            if ((i & 3) != 0 && p[i] != 0) atomicOr(&offbyte, 1);
        const int*   pi = (const int*)p;
        const float* pf = (const float*)p;
        for (int i = threadIdx.x; i < NTOK / 4; i += blockDim.x) {
            int iv = pi[i]; float fv = pf[i];
            if (iv != 0 && iv != 1)     atomicOr(&i32bad, 1);
            if (fv != 0.f && fv != 1.f) atomicOr(&f32bad, 1);
            if (fv == 1.f)              atomicOr(&f32one, 1);
        }
    }
    __syncthreads();
    if (threadIdx.x == 0) {
        int fmt;
        if (!offbyte && !i32bad)    fmt = 1;
        else if (!f32bad && f32one) fmt = 2;
        else                        fmt = 0;
        fmt_s = fmt;
    }
    __syncthreads();
    int fmt = fmt_s;
    for (int idx = threadIdx.x; idx < Bdim * Jm; idx += blockDim.x) {
        int b = idx / Jm, j = idx % Jm;
        int e = b * (Tdim * Jm) + j;
        bool sv, hv, gv;
        if (fmt == 0)      { sv = sm[e] != 0; hv = hm[e] != 0; gv = gm[e] != 0; }
        else if (fmt == 1) { sv = ((const int*)sm)[e] != 0; hv = ((const int*)hm)[e] != 0; gv = ((const int*)gm)[e] != 0; }
        else               { sv = ((const float*)sm)[e] != 0.f; hv = ((const float*)hm)[e] != 0.f; gv = ((const float*)gm)[e] != 0.f; }
        cat[idx] = sv ? 0 : (hv ? 1 : (gv ? 2 : 3));
    }
}

// ---------------- fused embed + LN1(layer0) + lora_tmp(layer0) ----------------
__global__ void embed_ln_tmp_kernel(const float* __restrict__ act,
                                    const int* __restrict__ m_idx, const int* __restrict__ cat,
                                    const float* __restrict__ Ws, const float* __restrict__ bs,
                                    const float* __restrict__ Wh, const float* __restrict__ bh,
                                    const float* __restrict__ Wg, const float* __restrict__ Wact,
                                    const float* __restrict__ pos,
                                    const float* __restrict__ lnS, const float* __restrict__ lnB,
                                    const float* __restrict__ lA,
                                    float* __restrict__ x, __nv_bfloat16* __restrict__ h,
                                    float* __restrict__ tmp)
{
    int warp = threadIdx.x >> 5, lane = threadIdx.x & 31;
    int token = blockIdx.x * 8 + warp;
    int j = token % Jm;
    int b = token / TOKPB;
    int m = m_idx[b];
    int ct = cat[b * Jm + j];
    float a = act[token];
    const float* posr = pos + ((size_t)m * Jm + j) * Hdim;
    const float* wgr  = Wg + (size_t)m * Hdim;

    float e[8];
    #pragma unroll
    for (int half = 0; half < 2; half++) {
        int c = (lane + half * 32) * 4;
        float4 r;
        if      (ct == 0) { float4 w = ld4(Ws, c), bb = ld4(bs, c);
                            r.x = a*w.x+bb.x; r.y = a*w.y+bb.y; r.z = a*w.z+bb.z; r.w = a*w.w+bb.w; }
        else if (ct == 1) { float4 w = ld4(Wh, c), bb = ld4(bh, c);
                            r.x = a*w.x+bb.x; r.y = a*w.y+bb.y; r.z = a*w.z+bb.z; r.w = a*w.w+bb.w; }
        else if (ct == 2) { float4 w = ld4(wgr, c);
                            r.x = a*w.x; r.y = a*w.y; r.z = a*w.z; r.w = a*w.w; }
        else              { r = make_float4(0.f, 0.f, 0.f, 0.f); }
        if (ct != 3) { float4 wa = ld4(Wact, c); r.x += wa.x; r.y += wa.y; r.z += wa.z; r.w += wa.w; }
        float4 p = ld4(posr, c);
        r.x += p.x; r.y += p.y; r.z += p.z; r.w += p.w;
        e[half*4+0] = r.x; e[half*4+1] = r.y; e[half*4+2] = r.z; e[half*4+3] = r.w;
        *(float4*)(x + (size_t)token * Hdim + c) = r;
    }

    float s = 0.f;
    #pragma unroll
    for (int q = 0; q < 8; q++) s += e[q];
    #pragma unroll
    for (int o = 16; o > 0; o >>= 1) s += __shfl_xor_sync(0xffffffffu, s, o);
    float mu = s * (1.f / Hdim);
    float v = 0.f;
    #pragma unroll
    for (int q = 0; q < 8; q++) { e[q] -= mu; v += e[q] * e[q]; }
    #pragma unroll
    for (int o = 16; o > 0; o >>= 1) v += __shfl_xor_sync(0xffffffffu, v, o);
    float rs = rsqrtf(v * (1.f / Hdim) + 1e-5f);

    float hv[8];
    #pragma unroll
    for (int half = 0; half < 2; half++) {
        int c = (lane + half * 32) * 4;
        float4 sc4 = ld4(lnS, c), bi4 = ld4(lnB, c);
        hv[half*4+0] = e[half*4+0] * rs * sc4.x + bi4.x;
        hv[half*4+1] = e[half*4+1] * rs * sc4.y + bi4.y;
        hv[half*4+2] = e[half*4+2] * rs * sc4.z + bi4.z;
        hv[half*4+3] = e[half*4+3] * rs * sc4.w + bi4.w;
        *(uint2*)(h + (size_t)token * Hdim + c) =
            make_uint2(pack2bf(hv[half*4+0], hv[half*4+1]), pack2bf(hv[half*4+2], hv[half*4+3]));
    }

    const float* Am = lA + (size_t)m * Hdim * RANKv;
    float t0=0,t1=0,t2=0,t3=0,t4=0,t5=0,t6=0,t7=0;
    #pragma unroll
    for (int q = 0; q < 8; q++) {
        int c = (lane + (q >> 2) * 32) * 4 + (q & 3);
        float4 a0 = ld4(Am + (size_t)c * RANKv, 0);
        float4 a1 = ld4(Am + (size_t)c * RANKv, 4);
        float hq = hv[q];
        t0 += hq * a0.x; t1 += hq * a0.y; t2 += hq * a0.z; t3 += hq * a0.w;
        t4 += hq * a1.x; t5 += hq * a1.y; t6 += hq * a1.z; t7 += hq * a1.w;
    }
    #pragma unroll
    for (int o = 16; o > 0; o >>= 1) {
        t0 += __shfl_xor_sync(0xffffffffu, t0, o);
        t1 += __shfl_xor_sync(0xffffffffu, t1, o);
        t2 += __shfl_xor_sync(0xffffffffu, t2, o);
        t3 += __shfl_xor_sync(0xffffffffu, t3, o);
        t4 += __shfl_xor_sync(0xffffffffu, t4, o);
        t5 += __shfl_xor_sync(0xffffffffu, t5, o);
        t6 += __shfl_xor_sync(0xffffffffu, t6, o);
        t7 += __shfl_xor_sync(0xffffffffu, t7, o);
    }
    if (lane == 0) {
        float* tp = tmp + (size_t)token * RANKv;
        *(float4*)tp       = make_float4(t0, t1, t2, t3);
        *(float4*)(tp + 4) = make_float4(t4, t5, t6, t7);
    }
}

// ---------------- attention: one CTA per (sequence, head); vectorized loads ----------------
#define APAD (DH + 2)

__global__ void attn_kernel(const __nv_bfloat16* __restrict__ qkv, __nv_bfloat16* __restrict__ o,
                            const int* __restrict__ m_idx)
{
    __shared__ float qs[Jm][APAD];
    __shared__ float ks[Jm][APAD];
    __shared__ float vs[Jm][APAD];
    __shared__ float sc[Jm][Jm + 1];
    int n = blockIdx.x, head = blockIdx.y;
    int b = n >> 7;
    int nj = c_nj[m_idx[b]];
    const float scale = 0.17677669529663687f;

    const __nv_bfloat16* base = qkv + (size_t)n * Jm * H3 + head * DH;
    #pragma unroll
    for (int it = 0; it < 9; it++) {
        int idx = threadIdx.x + it * 128;
        int seg = idx / 384;
        int rem = idx - seg * 384;
        int j = rem >> 4, c = (rem & 15) * 2;
        __nv_bfloat162 hv2 = *(const __nv_bfloat162*)(base + (size_t)j * H3 + seg * Hdim + c);
        float2 f = __bfloat1622float2(hv2);
        if (seg == 0)      { qs[j][c] = f.x * scale; qs[j][c + 1] = f.y * scale; }
        else if (seg == 1) { ks[j][c] = f.x;         ks[j][c + 1] = f.y; }
        else               { vs[j][c] = f.x;         vs[j][c + 1] = f.y; }
    }
    __syncthreads();

    for (int idx = threadIdx.x; idx < Jm * Jm; idx += blockDim.x) {
        int i = idx / Jm, j = idx % Jm;
        bool ok = (i < nj && j < nj) || (i == j);
        float s = -3.402823466e38f;
        if (ok) {
            s = 0.f;
            #pragma unroll
            for (int d = 0; d < DH; d++) s += qs[i][d] * ks[j][d];
        }
        sc[i][j] = s;
    }
    __syncthreads();
    if (threadIdx.x < Jm) {
        int i = threadIdx.x;
        float mx = -3.402823466e38f;
        #pragma unroll
        for (int j = 0; j < Jm; j++) mx = fmaxf(mx, sc[i][j]);
        float e[Jm]; float sum = 0.f;
        #pragma unroll
        for (int j = 0; j < Jm; j++) { e[j] = expf(sc[i][j] - mx); sum += e[j]; }
        float inv = 1.f / sum;
        #pragma unroll
        for (int j = 0; j < Jm; j++) sc[i][j] = e[j] * inv;
    }
    __syncthreads();
    for (int idx = threadIdx.x; idx < Jm * DH; idx += blockDim.x) {
        int i = idx >> 5, d = idx & 31;
        float a0 = 0.f;
        #pragma unroll
        for (int j = 0; j < Jm; j++) a0 += sc[i][j] * vs[j][d];
        o[((size_t)(n * Jm + i)) * Hdim + head * DH + d] = __float2bfloat16(a0);
    }
}

// ---------------- launcher ----------------
extern "C" void kernel_launch(void* const* d_in, const int* in_sizes, int n_in,
                              void* d_out, int out_size)
{
    (void)in_sizes; (void)n_in; (void)out_size;
    const float* act   = (const float*)d_in[0];
    const unsigned char* smk = (const unsigned char*)d_in[1];
    const unsigned char* hmk = (const unsigned char*)d_in[2];
    const unsigned char* gmk = (const unsigned char*)d_in[3];
    const int*   m_idx = (const int*)d_in[6];
    const float* Ws    = (const float*)d_in[7];
    const float* bs    = (const float*)d_in[8];
    const float* Wh    = (const float*)d_in[9];
    const float* bh    = (const float*)d_in[10];
    const float* Wg    = (const float*)d_in[11];
    const float* Wact  = (const float*)d_in[12];
    const float* pos   = (const float*)d_in[13];
    const float* ln1_s = (const float*)d_in[14];
    const float* ln1_b = (const float*)d_in[15];
    const float* Wqkv  = (const float*)d_in[16];
    const float* bqkv  = (const float*)d_in[17];
    const float* loraA = (const float*)d_in[18];
    const float* loraB = (const float*)d_in[19];
    const float* Wo    = (const float*)d_in[20];
    const float* bo    = (const float*)d_in[21];
    const float* ln2_s = (const float*)d_in[22];
    const float* ln2_b = (const float*)d_in[23];
    const float* W1    = (const float*)d_in[24];
    const float* b1    = (const float*)d_in[25];
    const float* W2    = (const float*)d_in[26];
    const float* b2    = (const float*)d_in[27];
    const float* g1    = (const float*)d_in[28];
    const float* g2    = (const float*)d_in[29];
    const float* lnf_s = (const float*)d_in[30];
    const float* lnf_b = (const float*)d_in[31];
    float* out = (float*)d_out;

    float *x, *tmp; __nv_bfloat16 *h, *qkv, *ob, *midb, *wt; int *cat;
    cudaGetSymbolAddress((void**)&x,    g_x);
    cudaGetSymbolAddress((void**)&h,    g_h);
    cudaGetSymbolAddress((void**)&qkv,  g_qkv);
    cudaGetSymbolAddress((void**)&ob,   g_o);
    cudaGetSymbolAddress((void**)&midb, g_midb);
    cudaGetSymbolAddress((void**)&tmp,  g_tmp);
    cudaGetSymbolAddress((void**)&wt,   g_wt);
    cudaGetSymbolAddress((void**)&cat,  g_cat);

    cudaFuncSetAttribute((const void*)hmma_gemm_kernel<1, 256>,               cudaFuncAttributeMaxDynamicSharedMemorySize, GSMEM);
    cudaFuncSetAttribute((const void*)hmma_gemm_kernel<3, 256>,               cudaFuncAttributeMaxDynamicSharedMemorySize, GSMEM);
    cudaFuncSetAttribute((const void*)hmma_ln_kernel<__nv_bfloat16, 256, 0>,  cudaFuncAttributeMaxDynamicSharedMemorySize, GSMEM2);
    cudaFuncSetAttribute((const void*)hmma_ln_kernel<__nv_bfloat16, 1024, 1>, cudaFuncAttributeMaxDynamicSharedMemorySize, GSMEM2);
    cudaFuncSetAttribute((const void*)hmma_ln_kernel<float, 1024, 0>,         cudaFuncAttributeMaxDynamicSharedMemorySize, GSMEM2);

    const size_t OFF_QKV = 0, OFF_WO = 196608, OFF_W1 = 262144, OFF_W2 = 524288, LSZ = 786432;

    transpose_all_kernel<<<dim3(768, 1, Lnum), dim3(32, 8)>>>(Wqkv, Wo, W1, W2, wt);
    detect_cat_kernel<<<1, 256>>>(smk, hmk, gmk, cat);
    embed_ln_tmp_kernel<<<NTOK / 8, 256>>>(act, m_idx, cat, Ws, bs, Wh, bh, Wg, Wact, pos,
                                           ln1_s, ln1_b, loraA, x, h, tmp);

    for (int l = 0; l < Lnum; l++) {
        // launch 4 on first iter: qkv GEMM (ncu target / clock canary)
        hmma_gemm_kernel<3, 256><<<dim3(H3 / 128, NTOK / 128), 256, GSMEM>>>(
            h, wt + l * LSZ + OFF_QKV, qkv, bqkv + l * H3,
            tmp, loraB + (size_t)l * Mnum * RANKv * H3, m_idx, H3);
        attn_kernel<<<dim3(NSEQ, HEADS), 128>>>(qkv, ob, m_idx);
        hmma_ln_kernel<__nv_bfloat16, 256, 0><<<dim3(1, NTOK / 64), 256, GSMEM2>>>(
            ob, wt + l * LSZ + OFF_WO, x, bo + l * Hdim, g1 + l * Hdim,
            ln2_s + l * Hdim, ln2_b + l * Hdim, h, nullptr, nullptr, nullptr);
        hmma_gemm_kernel<1, 256><<<dim3(H4 / 128, NTOK / 128), 256, GSMEM>>>(
            h, wt + l * LSZ + OFF_W1, midb, b1 + l * H4,
            nullptr, nullptr, nullptr, H4);
        if (l < Lnum - 1) {
            hmma_ln_kernel<__nv_bfloat16, 1024, 1><<<dim3(1, NTOK / 64), 256, GSMEM2>>>(
                midb, wt + l * LSZ + OFF_W2, x, b2 + l * Hdim, g2 + l * Hdim,
                ln1_s + (l + 1) * Hdim, ln1_b + (l + 1) * Hdim, h,
                loraA + (size_t)(l + 1) * Mnum * Hdim * RANKv, m_idx, tmp);
        } else {
            hmma_ln_kernel<float, 1024, 0><<<dim3(1, NTOK / 64), 256, GSMEM2>>>(
                midb, wt + l * LSZ + OFF_W2, x, b2 + l * Hdim, g2 + l * Hdim,
                lnf_s, lnf_b, out, nullptr, nullptr, nullptr);
        }
    }
}

// round 15
// speedup vs baseline: 1.5153x; 1.0063x over previous
#include <cuda_runtime.h>
#include <cuda_bf16.h>
#include <math.h>
#include <stdint.h>

// ---------------- problem constants ----------------
#define NTOK  49152
#define NSEQ  2048
#define Bdim  16
#define Tdim  128
#define Jm    24
#define Hdim  256
#define H3    768
#define H4    1024
#define Lnum  4
#define Mnum  12
#define RANKv 8
#define HEADS 8
#define DH    32
#define TOKPB 3072

__constant__ int c_nj[Mnum] = {8,10,12,14,16,18,20,22,24,9,13,17};

// ---------------- scratch ----------------
__device__ float         g_x   [(size_t)NTOK * Hdim];
__device__ __nv_bfloat16 g_h   [(size_t)NTOK * Hdim];
__device__ __nv_bfloat16 g_qkv [(size_t)NTOK * H3 ];
__device__ __nv_bfloat16 g_o   [(size_t)NTOK * Hdim];
__device__ __nv_bfloat16 g_midb[(size_t)NTOK * H4 ];
__device__ float         g_tmp [(size_t)NTOK * RANKv];
__device__ __nv_bfloat16 g_wt  [(size_t)Lnum * 786432];
__device__ int           g_cat [Bdim * Jm];

// ---------------- helpers ----------------
__device__ __forceinline__ uint32_t smem_u32(const void* p) {
    uint32_t a;
    asm("{ .reg .u64 t; cvta.to.shared.u64 t, %1; cvt.u32.u64 %0, t; }" : "=r"(a) : "l"(p));
    return a;
}
__device__ __forceinline__ void cp16(uint32_t dst, const void* src) {
    asm volatile("cp.async.cg.shared.global [%0], [%1], 16;" :: "r"(dst), "l"(src));
}
__device__ __forceinline__ void cp_commit() { asm volatile("cp.async.commit_group;"); }
__device__ __forceinline__ void ldm_x4(uint32_t& r0, uint32_t& r1, uint32_t& r2, uint32_t& r3, uint32_t a) {
    asm volatile("ldmatrix.sync.aligned.m8n8.x4.shared.b16 {%0,%1,%2,%3}, [%4];"
                 : "=r"(r0), "=r"(r1), "=r"(r2), "=r"(r3) : "r"(a));
}
__device__ __forceinline__ void mma16816(float* c, const uint32_t* a, const uint32_t* b) {
    asm volatile("mma.sync.aligned.m16n8k16.row.col.f32.bf16.bf16.f32 "
                 "{%0,%1,%2,%3},{%4,%5,%6,%7},{%8,%9},{%0,%1,%2,%3};"
                 : "+f"(c[0]), "+f"(c[1]), "+f"(c[2]), "+f"(c[3])
                 : "r"(a[0]), "r"(a[1]), "r"(a[2]), "r"(a[3]), "r"(b[0]), "r"(b[1]));
}
__device__ __forceinline__ uint32_t pack2bf(float x, float y) {
    __nv_bfloat162 h = __floats2bfloat162_rn(x, y);
    return *reinterpret_cast<uint32_t*>(&h);
}
__device__ __forceinline__ float gelu_tanh(float x) {
    float x3 = x * x * x;
    return 0.5f * x * (1.f + tanhf(0.7978845608028654f * (x + 0.044715f * x3)));
}
__device__ __forceinline__ float4 ld4(const float* p, int c) { return *(const float4*)(p + c); }

// ================= kernel 1: 128x128 HMMA GEMM (unchanged, proven) =================
#define TILE2  16384
#define NSTG   3
#define GSMEM  (NSTG * 2 * TILE2)    // 98304

template<int EPI, int KT>
__global__ void __launch_bounds__(256, 2)
hmma_gemm_kernel(const __nv_bfloat16* __restrict__ A, const __nv_bfloat16* __restrict__ Bt,
                 __nv_bfloat16* __restrict__ Cb,
                 const float* __restrict__ bias,
                 const float* __restrict__ ltmp, const float* __restrict__ lB,
                 const int* __restrict__ midx,
                 int N)
{
    extern __shared__ char dynsm[];
    constexpr int NCH = KT >> 6;

    int tid = threadIdx.x, lane = tid & 31, wid = tid >> 5;
    int wm = wid & 1, wn = wid >> 1;
    int brow = blockIdx.y * 128, bcol = blockIdx.x * 128;

    float acc[4][4][4];
    #pragma unroll
    for (int i = 0; i < 4; i++)
        #pragma unroll
        for (int j = 0; j < 4; j++)
            #pragma unroll
            for (int q = 0; q < 4; q++) acc[i][j][q] = 0.f;

    int lrow = tid >> 3, lcc = tid & 7;
    uint32_t soff0 = (uint32_t)(lrow * 128 + ((lcc ^ (lrow & 7)) * 16));
    const __nv_bfloat16* Ap0 = A + (size_t)(brow + lrow) * KT + lcc * 8;
    const __nv_bfloat16* Bp0 = Bt + (size_t)(bcol + lrow) * KT + lcc * 8;
    uint32_t smbase = smem_u32(dynsm);

    auto load_tiles = [&](int ch, int stage) {
        uint32_t da = smbase + (uint32_t)((stage * 2 + 0) * TILE2) + soff0;
        uint32_t db = smbase + (uint32_t)((stage * 2 + 1) * TILE2) + soff0;
        const __nv_bfloat16* Ah = Ap0 + ch * 64;
        const __nv_bfloat16* Bh = Bp0 + ch * 64;
        #pragma unroll
        for (int hh = 0; hh < 4; hh++) {
            cp16(da + hh * 4096, Ah + hh * 32 * KT);
            cp16(db + hh * 4096, Bh + hh * 32 * KT);
        }
        cp_commit();
    };

    int rsel = lane & 15, ksel = lane >> 4;
    uint32_t abase[4], bbase[2];
    #pragma unroll
    for (int mf = 0; mf < 4; mf++) {
        int ar = wm * 64 + mf * 16 + rsel;
        abase[mf] = (uint32_t)(ar * 128 + (ar & 7) * 16);
    }
    #pragma unroll
    for (int nf2 = 0; nf2 < 2; nf2++) {
        int br = wn * 32 + nf2 * 16 + rsel;
        bbase[nf2] = (uint32_t)(br * 128 + (br & 7) * 16);
    }

    load_tiles(0, 0);
    load_tiles(1, 1);

    #pragma unroll
    for (int ch = 0; ch < NCH; ch++) {
        asm volatile("cp.async.wait_group 1;");
        __syncthreads();

        uint32_t sa = smbase + (uint32_t)(((ch % NSTG) * 2 + 0) * TILE2);
        uint32_t sb = smbase + (uint32_t)(((ch % NSTG) * 2 + 1) * TILE2);

        #pragma unroll
        for (int ks = 0; ks < 4; ks++) {
            uint32_t cx = (uint32_t)((ks * 2 + ksel) * 16);
            uint32_t a[4][4];
            #pragma unroll
            for (int mf = 0; mf < 4; mf++)
                ldm_x4(a[mf][0], a[mf][1], a[mf][2], a[mf][3], sa + (abase[mf] ^ cx));
            uint32_t b[4][2];
            #pragma unroll
            for (int nf2 = 0; nf2 < 2; nf2++) {
                uint32_t r0, r1, r2, r3;
                ldm_x4(r0, r1, r2, r3, sb + (bbase[nf2] ^ cx));
                b[nf2 * 2 + 0][0] = r0; b[nf2 * 2 + 0][1] = r2;
                b[nf2 * 2 + 1][0] = r1; b[nf2 * 2 + 1][1] = r3;
            }
            #pragma unroll
            for (int mf = 0; mf < 4; mf++)
                #pragma unroll
                for (int nf = 0; nf < 4; nf++)
                    mma16816(acc[mf][nf], a[mf], b[nf]);
        }

        if (ch + 2 < NCH) load_tiles(ch + 2, (ch + 2) % NSTG);
        else              cp_commit();
    }

    float* lb_s  = (float*)dynsm;
    float* tmp_s = (float*)(dynsm + 4096);
    if (EPI == 3) {
        __syncthreads();
        int m = midx[brow / TOKPB];
        #pragma unroll
        for (int hh = 0; hh < 4; hh++) {
            int i = tid + hh * 256;
            int q = i >> 7, c = i & 127;
            lb_s[q * 128 + c] = lB[((size_t)m * RANKv + q) * N + bcol + c];
            int r = i >> 3, q2 = i & 7;
            tmp_s[r * 9 + q2] = ltmp[(size_t)(brow + r) * RANKv + q2];
        }
        __syncthreads();
    }

    int g = lane >> 2, tg = lane & 3;
    #pragma unroll
    for (int mf = 0; mf < 4; mf++) {
        int rl = wm * 64 + mf * 16 + g;
        int r0 = brow + rl;
        #pragma unroll
        for (int nf = 0; nf < 4; nf++) {
            int cl  = wn * 32 + nf * 8 + tg * 2;
            int col = bcol + cl;
            float b0 = bias[col], b1 = bias[col + 1];
            float v0 = acc[mf][nf][0] + b0, v1 = acc[mf][nf][1] + b1;
            float v2 = acc[mf][nf][2] + b0, v3 = acc[mf][nf][3] + b1;
            if (EPI == 1) {
                *(uint32_t*)(Cb + (size_t)r0 * N + col)       = pack2bf(gelu_tanh(v0), gelu_tanh(v1));
                *(uint32_t*)(Cb + (size_t)(r0 + 8) * N + col) = pack2bf(gelu_tanh(v2), gelu_tanh(v3));
            } else {
                float a00 = 0.f, a01 = 0.f, a10 = 0.f, a11 = 0.f;
                #pragma unroll
                for (int q = 0; q < 8; q++) {
                    float w0 = lb_s[q * 128 + cl], w1 = lb_s[q * 128 + cl + 1];
                    float u0 = tmp_s[rl * 9 + q], u1 = tmp_s[(rl + 8) * 9 + q];
                    a00 += u0 * w0; a01 += u0 * w1;
                    a10 += u1 * w0; a11 += u1 * w1;
                }
                *(uint32_t*)(Cb + (size_t)r0 * N + col)       = pack2bf(v0 + a00, v1 + a01);
                *(uint32_t*)(Cb + (size_t)(r0 + 8) * N + col) = pack2bf(v2 + a10, v3 + a11);
            }
        }
    }
}

// ================= kernel 2: 64x256 HMMA GEMM + residual + fused LN (+ lora) ===========
#define TA64   8192
#define TB256  32768
#define STG64  (TA64 + TB256)        // 40960
#define GSMEM2 (2 * STG64)           // 81920

template<typename TO, int KT, int DOLORA, int WRITEX>
__global__ void __launch_bounds__(256, 2)
hmma_ln_kernel(const __nv_bfloat16* __restrict__ A, const __nv_bfloat16* __restrict__ Bt,
               float* __restrict__ C,
               const float* __restrict__ bias, const float* __restrict__ gsc,
               const float* __restrict__ lnS, const float* __restrict__ lnB,
               TO* __restrict__ Hout,
               const float* __restrict__ lA, const int* __restrict__ midx,
               float* __restrict__ tmp)
{
    extern __shared__ char dynsm[];
    const int N = 256;
    constexpr int NCH = KT >> 6;

    int tid = threadIdx.x, lane = tid & 31, wid = tid >> 5;
    int wm = wid & 1, wn = wid >> 1;
    int brow = blockIdx.y * 64;

    float acc[2][8][4];
    #pragma unroll
    for (int i = 0; i < 2; i++)
        #pragma unroll
        for (int j = 0; j < 8; j++)
            #pragma unroll
            for (int q = 0; q < 4; q++) acc[i][j][q] = 0.f;

    int lrow = tid >> 3, lcc = tid & 7;
    uint32_t soff0 = (uint32_t)(lrow * 128 + ((lcc ^ (lrow & 7)) * 16));
    const __nv_bfloat16* Ap0 = A + (size_t)(brow + lrow) * KT + lcc * 8;
    const __nv_bfloat16* Bp0 = Bt + (size_t)lrow * KT + lcc * 8;
    uint32_t smbase = smem_u32(dynsm);

    auto load_tiles = [&](int ch, int stage) {
        uint32_t da = smbase + (uint32_t)(stage * STG64) + soff0;
        uint32_t db = da + TA64;
        const __nv_bfloat16* Ah = Ap0 + ch * 64;
        const __nv_bfloat16* Bh = Bp0 + ch * 64;
        #pragma unroll
        for (int hh = 0; hh < 2; hh++)
            cp16(da + hh * 4096, Ah + hh * 32 * KT);
        #pragma unroll
        for (int hh = 0; hh < 8; hh++)
            cp16(db + hh * 4096, Bh + hh * 32 * KT);
        cp_commit();
    };

    int rsel = lane & 15, ksel = lane >> 4;
    uint32_t abase[2], bbase[4];
    #pragma unroll
    for (int mf = 0; mf < 2; mf++) {
        int ar = wm * 32 + mf * 16 + rsel;
        abase[mf] = (uint32_t)(ar * 128 + (ar & 7) * 16);
    }
    #pragma unroll
    for (int nf2 = 0; nf2 < 4; nf2++) {
        int br = wn * 64 + nf2 * 16 + rsel;
        bbase[nf2] = (uint32_t)(br * 128 + (br & 7) * 16);
    }

    load_tiles(0, 0);

    for (int ch = 0; ch < NCH; ch++) {
        if (ch + 1 < NCH) {
            load_tiles(ch + 1, (ch + 1) & 1);
            asm volatile("cp.async.wait_group 1;");
        } else {
            asm volatile("cp.async.wait_group 0;");
        }
        __syncthreads();

        uint32_t sa = smbase + (uint32_t)((ch & 1) * STG64);
        uint32_t sb = sa + TA64;

        #pragma unroll
        for (int ks = 0; ks < 4; ks++) {
            uint32_t cx = (uint32_t)((ks * 2 + ksel) * 16);
            uint32_t a[2][4];
            #pragma unroll
            for (int mf = 0; mf < 2; mf++)
                ldm_x4(a[mf][0], a[mf][1], a[mf][2], a[mf][3], sa + (abase[mf] ^ cx));
            uint32_t b[8][2];
            #pragma unroll
            for (int nf2 = 0; nf2 < 4; nf2++) {
                uint32_t r0, r1, r2, r3;
                ldm_x4(r0, r1, r2, r3, sb + (bbase[nf2] ^ cx));
                b[nf2 * 2 + 0][0] = r0; b[nf2 * 2 + 0][1] = r2;
                b[nf2 * 2 + 1][0] = r1; b[nf2 * 2 + 1][1] = r3;
            }
            #pragma unroll
            for (int mf = 0; mf < 2; mf++)
                #pragma unroll
                for (int nf = 0; nf < 8; nf++)
                    mma16816(acc[mf][nf], a[mf], b[nf]);
        }
        __syncthreads();
    }

    int g = lane >> 2, tg = lane & 3;

    // residual rmw; updated x stays in acc (final layer: skip writeback)
    #pragma unroll
    for (int mf = 0; mf < 2; mf++) {
        int r0 = brow + wm * 32 + mf * 16 + g;
        #pragma unroll
        for (int nf = 0; nf < 8; nf++) {
            int col = wn * 64 + nf * 8 + tg * 2;
            float b0 = bias[col], b1 = bias[col + 1];
            float s0 = gsc[col],  s1 = gsc[col + 1];
            float2 o0 = *(float2*)(C + (size_t)r0 * N + col);
            float2 o1 = *(float2*)(C + (size_t)(r0 + 8) * N + col);
            o0.x += s0 * (acc[mf][nf][0] + b0); o0.y += s1 * (acc[mf][nf][1] + b1);
            o1.x += s0 * (acc[mf][nf][2] + b0); o1.y += s1 * (acc[mf][nf][3] + b1);
            if (WRITEX) {
                *(float2*)(C + (size_t)r0 * N + col)       = o0;
                *(float2*)(C + (size_t)(r0 + 8) * N + col) = o1;
            }
            acc[mf][nf][0] = o0.x; acc[mf][nf][1] = o0.y;
            acc[mf][nf][2] = o1.x; acc[mf][nf][3] = o1.y;
        }
    }

    float* ssum = (float*)dynsm;         // [64][4]
    float* ssq  = ssum + 256;            // [64][4]
    float* smu  = ssq + 256;             // [64]
    float* srs  = smu + 64;              // [64]
    float* laS  = srs + 64;              // [256][8]  (DOLORA)
    float* red  = laS + 2048;            // [64][8][4] (DOLORA)
    __syncthreads();

    #pragma unroll
    for (int mf = 0; mf < 2; mf++) {
        #pragma unroll
        for (int half = 0; half < 2; half++) {
            float ps = 0.f, pq = 0.f;
            #pragma unroll
            for (int nf = 0; nf < 8; nf++) {
                float v0 = acc[mf][nf][half * 2 + 0];
                float v1 = acc[mf][nf][half * 2 + 1];
                ps += v0 + v1;
                pq += v0 * v0 + v1 * v1;
            }
            ps += __shfl_xor_sync(0xffffffffu, ps, 1);
            pq += __shfl_xor_sync(0xffffffffu, pq, 1);
            ps += __shfl_xor_sync(0xffffffffu, ps, 2);
            pq += __shfl_xor_sync(0xffffffffu, pq, 2);
            if (tg == 0) {
                int rl = wm * 32 + mf * 16 + half * 8 + g;
                ssum[rl * 4 + wn] = ps;
                ssq [rl * 4 + wn] = pq;
            }
        }
    }
    if (DOLORA) {
        int m = midx[brow / TOKPB];
        const float4* Am4 = (const float4*)(lA + (size_t)m * Hdim * RANKv);
        float4* laS4 = (float4*)laS;
        laS4[tid]       = Am4[tid];
        laS4[tid + 256] = Am4[tid + 256];
    }
    __syncthreads();
    if (tid < 64) {
        float s = ssum[tid * 4] + ssum[tid * 4 + 1] + ssum[tid * 4 + 2] + ssum[tid * 4 + 3];
        float q = ssq [tid * 4] + ssq [tid * 4 + 1] + ssq [tid * 4 + 2] + ssq [tid * 4 + 3];
        float mu = s * (1.f / 256.f);
        float var = fmaxf(q * (1.f / 256.f) - mu * mu, 0.f);
        smu[tid] = mu;
        srs[tid] = rsqrtf(var + 1e-5f);
    }
    __syncthreads();

    #pragma unroll
    for (int mf = 0; mf < 2; mf++) {
        int rl = wm * 32 + mf * 16 + g;
        float mu0 = smu[rl],     rs0 = srs[rl];
        float mu1 = smu[rl + 8], rs1 = srs[rl + 8];
        int r0 = brow + rl;
        float p0[RANKv], p1[RANKv];
        if (DOLORA) {
            #pragma unroll
            for (int r = 0; r < RANKv; r++) { p0[r] = 0.f; p1[r] = 0.f; }
        }
        #pragma unroll
        for (int nf = 0; nf < 8; nf++) {
            int col = wn * 64 + nf * 8 + tg * 2;
            float sc0 = lnS[col], sc1 = lnS[col + 1];
            float bi0 = lnB[col], bi1 = lnB[col + 1];
            float h0 = (acc[mf][nf][0] - mu0) * rs0 * sc0 + bi0;
            float h1 = (acc[mf][nf][1] - mu0) * rs0 * sc1 + bi1;
            float h2 = (acc[mf][nf][2] - mu1) * rs1 * sc0 + bi0;
            float h3 = (acc[mf][nf][3] - mu1) * rs1 * sc1 + bi1;
            if (DOLORA) {
                const float* l0 = laS + col * RANKv;
                const float* l1 = laS + (col + 1) * RANKv;
                #pragma unroll
                for (int r = 0; r < RANKv; r++) {
                    p0[r] += h0 * l0[r] + h1 * l1[r];
                    p1[r] += h2 * l0[r] + h3 * l1[r];
                }
            }
            if constexpr (sizeof(TO) == 2) {
                *(uint32_t*)((__nv_bfloat16*)Hout + (size_t)r0 * N + col)       = pack2bf(h0, h1);
                *(uint32_t*)((__nv_bfloat16*)Hout + (size_t)(r0 + 8) * N + col) = pack2bf(h2, h3);
            } else {
                *(float2*)((float*)Hout + (size_t)r0 * N + col)       = make_float2(h0, h1);
                *(float2*)((float*)Hout + (size_t)(r0 + 8) * N + col) = make_float2(h2, h3);
            }
        }
        if (DOLORA) {
            #pragma unroll
            for (int r = 0; r < RANKv; r++) {
                p0[r] += __shfl_xor_sync(0xffffffffu, p0[r], 1);
                p0[r] += __shfl_xor_sync(0xffffffffu, p0[r], 2);
                p1[r] += __shfl_xor_sync(0xffffffffu, p1[r], 1);
                p1[r] += __shfl_xor_sync(0xffffffffu, p1[r], 2);
            }
            if (tg == 0) {
                #pragma unroll
                for (int r = 0; r < RANKv; r++) {
                    red[(rl * RANKv + r) * 4 + wn]       = p0[r];
                    red[((rl + 8) * RANKv + r) * 4 + wn] = p1[r];
                }
            }
        }
    }

    if (DOLORA) {
        __syncthreads();
        #pragma unroll
        for (int hh = 0; hh < 2; hh++) {
            int i = tid + hh * 256;
            int row = i >> 3, r = i & 7;
            float4 v = *(float4*)(red + i * 4);
            tmp[(size_t)(brow + row) * RANKv + r] = v.x + v.y + v.z + v.w;
        }
    }
}

// ---------------- merged weight transpose + mask detect (one launch) ----------------
// grid (769, 1, Lnum); bx<768: transpose sections; bx==768 && z==0: mask detect
__global__ void prep_kernel(const float* __restrict__ Wqkv, const float* __restrict__ Wo,
                            const float* __restrict__ W1,   const float* __restrict__ W2,
                            __nv_bfloat16* __restrict__ wt,
                            const unsigned char* __restrict__ sm,
                            const unsigned char* __restrict__ hm,
                            const unsigned char* __restrict__ gm,
                            int* __restrict__ cat)
{
    const size_t LSZ = 786432, OFF_WO = 196608, OFF_W1 = 262144, OFF_W2 = 524288;
    int bx = blockIdx.x, l = blockIdx.z;
    int tid = threadIdx.x;

    if (bx == 768) {
        if (l != 0) return;
        __shared__ int offbyte, i32bad, f32bad, f32one, fmt_s;
        if (tid == 0) { offbyte = 0; i32bad = 0; f32bad = 0; f32one = 0; }
        __syncthreads();
        const unsigned char* bufs[3] = {sm, hm, gm};
        for (int bi = 0; bi < 3; bi++) {
            const unsigned char* p = bufs[bi];
            for (int i = tid; i < NTOK; i += blockDim.x)
                if ((i & 3) != 0 && p[i] != 0) atomicOr(&offbyte, 1);
            const int*   pi = (const int*)p;
            const float* pf = (const float*)p;
            for (int i = tid; i < NTOK / 4; i += blockDim.x) {
                int iv = pi[i]; float fv = pf[i];
                if (iv != 0 && iv != 1)     atomicOr(&i32bad, 1);
                if (fv != 0.f && fv != 1.f) atomicOr(&f32bad, 1);
                if (fv == 1.f)              atomicOr(&f32one, 1);
            }
        }
        __syncthreads();
        if (tid == 0) {
            int fmt;
            if (!offbyte && !i32bad)    fmt = 1;
            else if (!f32bad && f32one) fmt = 2;
            else                        fmt = 0;
            fmt_s = fmt;
        }
        __syncthreads();
        int fmt = fmt_s;
        for (int idx = tid; idx < Bdim * Jm; idx += blockDim.x) {
            int b = idx / Jm, j = idx % Jm;
            int e = b * (Tdim * Jm) + j;
            bool sv, hv, gv;
            if (fmt == 0)      { sv = sm[e] != 0; hv = hm[e] != 0; gv = gm[e] != 0; }
            else if (fmt == 1) { sv = ((const int*)sm)[e] != 0; hv = ((const int*)hm)[e] != 0; gv = ((const int*)gm)[e] != 0; }
            else               { sv = ((const float*)sm)[e] != 0.f; hv = ((const float*)hm)[e] != 0.f; gv = ((const float*)gm)[e] != 0.f; }
            cat[idx] = sv ? 0 : (hv ? 1 : (gv ? 2 : 3));
        }
        return;
    }

    const float* src; __nv_bfloat16* dst; int K, N, tx, ty;
    if (bx < 192)      { int r = bx;       ty = r / 24, tx = r % 24; K = 256;  N = 768;
                         src = Wqkv + (size_t)l * 196608; dst = wt + l * LSZ; }
    else if (bx < 256) { int r = bx - 192; ty = r / 8,  tx = r % 8;  K = 256;  N = 256;
                         src = Wo + (size_t)l * 65536;   dst = wt + l * LSZ + OFF_WO; }
    else if (bx < 512) { int r = bx - 256; ty = r / 32, tx = r % 32; K = 256;  N = 1024;
                         src = W1 + (size_t)l * 262144;  dst = wt + l * LSZ + OFF_W1; }
    else               { int r = bx - 512; ty = r / 8,  tx = r % 8;  K = 1024; N = 256;
                         src = W2 + (size_t)l * 262144;  dst = wt + l * LSZ + OFF_W2; }

    __shared__ float t[32][33];
    int kb = ty * 32, nb = tx * 32;
    int x = tid & 31, y = tid >> 5;
    #pragma unroll
    for (int i = 0; i < 32; i += 8)
        t[y + i][x] = src[(size_t)(kb + y + i) * N + nb + x];
    __syncthreads();
    #pragma unroll
    for (int i = 0; i < 32; i += 8)
        dst[(size_t)(nb + y + i) * K + kb + x] = __float2bfloat16(t[x][y + i]);
}

// ---------------- fused embed + LN1(layer0) + lora_tmp(layer0) ----------------
__global__ void embed_ln_tmp_kernel(const float* __restrict__ act,
                                    const int* __restrict__ m_idx, const int* __restrict__ cat,
                                    const float* __restrict__ Ws, const float* __restrict__ bs,
                                    const float* __restrict__ Wh, const float* __restrict__ bh,
                                    const float* __restrict__ Wg, const float* __restrict__ Wact,
                                    const float* __restrict__ pos,
                                    const float* __restrict__ lnS, const float* __restrict__ lnB,
                                    const float* __restrict__ lA,
                                    float* __restrict__ x, __nv_bfloat16* __restrict__ h,
                                    float* __restrict__ tmp)
{
    int warp = threadIdx.x >> 5, lane = threadIdx.x & 31;
    int token = blockIdx.x * 8 + warp;
    int j = token % Jm;
    int b = token / TOKPB;
    int m = m_idx[b];
    int ct = cat[b * Jm + j];
    float a = act[token];
    const float* posr = pos + ((size_t)m * Jm + j) * Hdim;
    const float* wgr  = Wg + (size_t)m * Hdim;

    float e[8];
    #pragma unroll
    for (int half = 0; half < 2; half++) {
        int c = (lane + half * 32) * 4;
        float4 r;
        if      (ct == 0) { float4 w = ld4(Ws, c), bb = ld4(bs, c);
                            r.x = a*w.x+bb.x; r.y = a*w.y+bb.y; r.z = a*w.z+bb.z; r.w = a*w.w+bb.w; }
        else if (ct == 1) { float4 w = ld4(Wh, c), bb = ld4(bh, c);
                            r.x = a*w.x+bb.x; r.y = a*w.y+bb.y; r.z = a*w.z+bb.z; r.w = a*w.w+bb.w; }
        else if (ct == 2) { float4 w = ld4(wgr, c);
                            r.x = a*w.x; r.y = a*w.y; r.z = a*w.z; r.w = a*w.w; }
        else              { r = make_float4(0.f, 0.f, 0.f, 0.f); }
        if (ct != 3) { float4 wa = ld4(Wact, c); r.x += wa.x; r.y += wa.y; r.z += wa.z; r.w += wa.w; }
        float4 p = ld4(posr, c);
        r.x += p.x; r.y += p.y; r.z += p.z; r.w += p.w;
        e[half*4+0] = r.x; e[half*4+1] = r.y; e[half*4+2] = r.z; e[half*4+3] = r.w;
        *(float4*)(x + (size_t)token * Hdim + c) = r;
    }

    float s = 0.f;
    #pragma unroll
    for (int q = 0; q < 8; q++) s += e[q];
    #pragma unroll
    for (int o = 16; o > 0; o >>= 1) s += __shfl_xor_sync(0xffffffffu, s, o);
    float mu = s * (1.f / Hdim);
    float v = 0.f;
    #pragma unroll
    for (int q = 0; q < 8; q++) { e[q] -= mu; v += e[q] * e[q]; }
    #pragma unroll
    for (int o = 16; o > 0; o >>= 1) v += __shfl_xor_sync(0xffffffffu, v, o);
    float rs = rsqrtf(v * (1.f / Hdim) + 1e-5f);

    float hv[8];
    #pragma unroll
    for (int half = 0; half < 2; half++) {
        int c = (lane + half * 32) * 4;
        float4 sc4 = ld4(lnS, c), bi4 = ld4(lnB, c);
        hv[half*4+0] = e[half*4+0] * rs * sc4.x + bi4.x;
        hv[half*4+1] = e[half*4+1] * rs * sc4.y + bi4.y;
        hv[half*4+2] = e[half*4+2] * rs * sc4.z + bi4.z;
        hv[half*4+3] = e[half*4+3] * rs * sc4.w + bi4.w;
        *(uint2*)(h + (size_t)token * Hdim + c) =
            make_uint2(pack2bf(hv[half*4+0], hv[half*4+1]), pack2bf(hv[half*4+2], hv[half*4+3]));
    }

    const float* Am = lA + (size_t)m * Hdim * RANKv;
    float t0=0,t1=0,t2=0,t3=0,t4=0,t5=0,t6=0,t7=0;
    #pragma unroll
    for (int q = 0; q < 8; q++) {
        int c = (lane + (q >> 2) * 32) * 4 + (q & 3);
        float4 a0 = ld4(Am + (size_t)c * RANKv, 0);
        float4 a1 = ld4(Am + (size_t)c * RANKv, 4);
        float hq = hv[q];
        t0 += hq * a0.x; t1 += hq * a0.y; t2 += hq * a0.z; t3 += hq * a0.w;
        t4 += hq * a1.x; t5 += hq * a1.y; t6 += hq * a1.z; t7 += hq * a1.w;
    }
    #pragma unroll
    for (int o = 16; o > 0; o >>= 1) {
        t0 += __shfl_xor_sync(0xffffffffu, t0, o);
        t1 += __shfl_xor_sync(0xffffffffu, t1, o);
        t2 += __shfl_xor_sync(0xffffffffu, t2, o);
        t3 += __shfl_xor_sync(0xffffffffu, t3, o);
        t4 += __shfl_xor_sync(0xffffffffu, t4, o);
        t5 += __shfl_xor_sync(0xffffffffu, t5, o);
        t6 += __shfl_xor_sync(0xffffffffu, t6, o);
        t7 += __shfl_xor_sync(0xffffffffu, t7, o);
    }
    if (lane == 0) {
        float* tp = tmp + (size_t)token * RANKv;
        *(float4*)tp       = make_float4(t0, t1, t2, t3);
        *(float4*)(tp + 4) = make_float4(t4, t5, t6, t7);
    }
}

// ---------------- attention ----------------
#define APAD (DH + 2)

__global__ void attn_kernel(const __nv_bfloat16* __restrict__ qkv, __nv_bfloat16* __restrict__ o,
                            const int* __restrict__ m_idx)
{
    __shared__ float qs[Jm][APAD];
    __shared__ float ks[Jm][APAD];
    __shared__ float vs[Jm][APAD];
    __shared__ float sc[Jm][Jm + 1];
    int n = blockIdx.x, head = blockIdx.y;
    int b = n >> 7;
    int nj = c_nj[m_idx[b]];
    const float scale = 0.17677669529663687f;

    const __nv_bfloat16* base = qkv + (size_t)n * Jm * H3 + head * DH;
    #pragma unroll
    for (int it = 0; it < 9; it++) {
        int idx = threadIdx.x + it * 128;
        int seg = idx / 384;
        int rem = idx - seg * 384;
        int j = rem >> 4, c = (rem & 15) * 2;
        __nv_bfloat162 hv2 = *(const __nv_bfloat162*)(base + (size_t)j * H3 + seg * Hdim + c);
        float2 f = __bfloat1622float2(hv2);
        if (seg == 0)      { qs[j][c] = f.x * scale; qs[j][c + 1] = f.y * scale; }
        else if (seg == 1) { ks[j][c] = f.x;         ks[j][c + 1] = f.y; }
        else               { vs[j][c] = f.x;         vs[j][c + 1] = f.y; }
    }
    __syncthreads();

    for (int idx = threadIdx.x; idx < Jm * Jm; idx += blockDim.x) {
        int i = idx / Jm, j = idx % Jm;
        bool ok = (i < nj && j < nj) || (i == j);
        float s = -3.402823466e38f;
        if (ok) {
            s = 0.f;
            #pragma unroll
            for (int d = 0; d < DH; d++) s += qs[i][d] * ks[j][d];
        }
        sc[i][j] = s;
    }
    __syncthreads();
    if (threadIdx.x < Jm) {
        int i = threadIdx.x;
        float mx = -3.402823466e38f;
        #pragma unroll
        for (int j = 0; j < Jm; j++) mx = fmaxf(mx, sc[i][j]);
        float e[Jm]; float sum = 0.f;
        #pragma unroll
        for (int j = 0; j < Jm; j++) { e[j] = expf(sc[i][j] - mx); sum += e[j]; }
        float inv = 1.f / sum;
        #pragma unroll
        for (int j = 0; j < Jm; j++) sc[i][j] = e[j] * inv;
    }
    __syncthreads();
    for (int idx = threadIdx.x; idx < Jm * DH; idx += blockDim.x) {
        int i = idx >> 5, d = idx & 31;
        float a0 = 0.f;
        #pragma unroll
        for (int j = 0; j < Jm; j++) a0 += sc[i][j] * vs[j][d];
        o[((size_t)(n * Jm + i)) * Hdim + head * DH + d] = __float2bfloat16(a0);
    }
}

// ---------------- launcher ----------------
extern "C" void kernel_launch(void* const* d_in, const int* in_sizes, int n_in,
                              void* d_out, int out_size)
{
    (void)in_sizes; (void)n_in; (void)out_size;
    const float* act   = (const float*)d_in[0];
    const unsigned char* smk = (const unsigned char*)d_in[1];
    const unsigned char* hmk = (const unsigned char*)d_in[2];
    const unsigned char* gmk = (const unsigned char*)d_in[3];
    const int*   m_idx = (const int*)d_in[6];
    const float* Ws    = (const float*)d_in[7];
    const float* bs    = (const float*)d_in[8];
    const float* Wh    = (const float*)d_in[9];
    const float* bh    = (const float*)d_in[10];
    const float* Wg    = (const float*)d_in[11];
    const float* Wact  = (const float*)d_in[12];
    const float* pos   = (const float*)d_in[13];
    const float* ln1_s = (const float*)d_in[14];
    const float* ln1_b = (const float*)d_in[15];
    const float* Wqkv  = (const float*)d_in[16];
    const float* bqkv  = (const float*)d_in[17];
    const float* loraA = (const float*)d_in[18];
    const float* loraB = (const float*)d_in[19];
    const float* Wo    = (const float*)d_in[20];
    const float* bo    = (const float*)d_in[21];
    const float* ln2_s = (const float*)d_in[22];
    const float* ln2_b = (const float*)d_in[23];
    const float* W1    = (const float*)d_in[24];
    const float* b1    = (const float*)d_in[25];
    const float* W2    = (const float*)d_in[26];
    const float* b2    = (const float*)d_in[27];
    const float* g1    = (const float*)d_in[28];
    const float* g2    = (const float*)d_in[29];
    const float* lnf_s = (const float*)d_in[30];
    const float* lnf_b = (const float*)d_in[31];
    float* out = (float*)d_out;

    float *x, *tmp; __nv_bfloat16 *h, *qkv, *ob, *midb, *wt; int *cat;
    cudaGetSymbolAddress((void**)&x,    g_x);
    cudaGetSymbolAddress((void**)&h,    g_h);
    cudaGetSymbolAddress((void**)&qkv,  g_qkv);
    cudaGetSymbolAddress((void**)&ob,   g_o);
    cudaGetSymbolAddress((void**)&midb, g_midb);
    cudaGetSymbolAddress((void**)&tmp,  g_tmp);
    cudaGetSymbolAddress((void**)&wt,   g_wt);
    cudaGetSymbolAddress((void**)&cat,  g_cat);

    cudaFuncSetAttribute((const void*)hmma_gemm_kernel<1, 256>,                  cudaFuncAttributeMaxDynamicSharedMemorySize, GSMEM);
    cudaFuncSetAttribute((const void*)hmma_gemm_kernel<3, 256>,                  cudaFuncAttributeMaxDynamicSharedMemorySize, GSMEM);
    cudaFuncSetAttribute((const void*)hmma_ln_kernel<__nv_bfloat16, 256, 0, 1>,  cudaFuncAttributeMaxDynamicSharedMemorySize, GSMEM2);
    cudaFuncSetAttribute((const void*)hmma_ln_kernel<__nv_bfloat16, 1024, 1, 1>, cudaFuncAttributeMaxDynamicSharedMemorySize, GSMEM2);
    cudaFuncSetAttribute((const void*)hmma_ln_kernel<float, 1024, 0, 0>,         cudaFuncAttributeMaxDynamicSharedMemorySize, GSMEM2);

    const size_t OFF_QKV = 0, OFF_WO = 196608, OFF_W1 = 262144, OFF_W2 = 524288, LSZ = 786432;

    // launch 1: transposes + mask detect merged
    prep_kernel<<<dim3(769, 1, Lnum), 256>>>(Wqkv, Wo, W1, W2, wt, smk, hmk, gmk, cat);
    // launch 2: embed + LN1(l0) + lora_tmp(l0)
    embed_ln_tmp_kernel<<<NTOK / 8, 256>>>(act, m_idx, cat, Ws, bs, Wh, bh, Wg, Wact, pos,
                                           ln1_s, ln1_b, loraA, x, h, tmp);

    for (int l = 0; l < Lnum; l++) {
        // launch 3 (first iter): qkv GEMM
        hmma_gemm_kernel<3, 256><<<dim3(H3 / 128, NTOK / 128), 256, GSMEM>>>(
            h, wt + l * LSZ + OFF_QKV, qkv, bqkv + l * H3,
            tmp, loraB + (size_t)l * Mnum * RANKv * H3, m_idx, H3);
        // launch 4 (first iter): attention -> ncu target this round
        attn_kernel<<<dim3(NSEQ, HEADS), 128>>>(qkv, ob, m_idx);
        hmma_ln_kernel<__nv_bfloat16, 256, 0, 1><<<dim3(1, NTOK / 64), 256, GSMEM2>>>(
            ob, wt + l * LSZ + OFF_WO, x, bo + l * Hdim, g1 + l * Hdim,
            ln2_s + l * Hdim, ln2_b + l * Hdim, h, nullptr, nullptr, nullptr);
        hmma_gemm_kernel<1, 256><<<dim3(H4 / 128, NTOK / 128), 256, GSMEM>>>(
            h, wt + l * LSZ + OFF_W1, midb, b1 + l * H4,
            nullptr, nullptr, nullptr, H4);
        if (l < Lnum - 1) {
            hmma_ln_kernel<__nv_bfloat16, 1024, 1, 1><<<dim3(1, NTOK / 64), 256, GSMEM2>>>(
                midb, wt + l * LSZ + OFF_W2, x, b2 + l * Hdim, g2 + l * Hdim,
                ln1_s + (l + 1) * Hdim, ln1_b + (l + 1) * Hdim, h,
                loraA + (size_t)(l + 1) * Mnum * Hdim * RANKv, m_idx, tmp);
        } else {
            hmma_ln_kernel<float, 1024, 0, 0><<<dim3(1, NTOK / 64), 256, GSMEM2>>>(
                midb, wt + l * LSZ + OFF_W2, x, b2 + l * Hdim, g2 + l * Hdim,
                lnf_s, lnf_b, out, nullptr, nullptr, nullptr);
        }
    }
}

// round 16
// speedup vs baseline: 1.5875x; 1.0476x over previous
#include <cuda_runtime.h>
#include <cuda_bf16.h>
#include <math.h>
#include <stdint.h>

// ---------------- problem constants ----------------
#define NTOK  49152
#define NSEQ  2048
#define Bdim  16
#define Tdim  128
#define Jm    24
#define Hdim  256
#define H3    768
#define H4    1024
#define Lnum  4
#define Mnum  12
#define RANKv 8
#define HEADS 8
#define DH    32
#define TOKPB 3072

__constant__ int c_nj[Mnum] = {8,10,12,14,16,18,20,22,24,9,13,17};

// ---------------- scratch ----------------
__device__ float         g_x   [(size_t)NTOK * Hdim];
__device__ __nv_bfloat16 g_h   [(size_t)NTOK * Hdim];
__device__ __nv_bfloat16 g_qkv [(size_t)NTOK * H3 ];
__device__ __nv_bfloat16 g_o   [(size_t)NTOK * Hdim];
__device__ __nv_bfloat16 g_midb[(size_t)NTOK * H4 ];
__device__ float         g_tmp [(size_t)NTOK * RANKv];
__device__ __nv_bfloat16 g_wt  [(size_t)Lnum * 786432];
__device__ int           g_cat [Bdim * Jm];

// ---------------- helpers ----------------
__device__ __forceinline__ uint32_t smem_u32(const void* p) {
    uint32_t a;
    asm("{ .reg .u64 t; cvta.to.shared.u64 t, %1; cvt.u32.u64 %0, t; }" : "=r"(a) : "l"(p));
    return a;
}
__device__ __forceinline__ void cp16(uint32_t dst, const void* src) {
    asm volatile("cp.async.cg.shared.global [%0], [%1], 16;" :: "r"(dst), "l"(src));
}
__device__ __forceinline__ void cp_commit() { asm volatile("cp.async.commit_group;"); }
__device__ __forceinline__ void ldm_x4(uint32_t& r0, uint32_t& r1, uint32_t& r2, uint32_t& r3, uint32_t a) {
    asm volatile("ldmatrix.sync.aligned.m8n8.x4.shared.b16 {%0,%1,%2,%3}, [%4];"
                 : "=r"(r0), "=r"(r1), "=r"(r2), "=r"(r3) : "r"(a));
}
__device__ __forceinline__ void mma16816(float* c, const uint32_t* a, const uint32_t* b) {
    asm volatile("mma.sync.aligned.m16n8k16.row.col.f32.bf16.bf16.f32 "
                 "{%0,%1,%2,%3},{%4,%5,%6,%7},{%8,%9},{%0,%1,%2,%3};"
                 : "+f"(c[0]), "+f"(c[1]), "+f"(c[2]), "+f"(c[3])
                 : "r"(a[0]), "r"(a[1]), "r"(a[2]), "r"(a[3]), "r"(b[0]), "r"(b[1]));
}
__device__ __forceinline__ uint32_t pack2bf(float x, float y) {
    __nv_bfloat162 h = __floats2bfloat162_rn(x, y);
    return *reinterpret_cast<uint32_t*>(&h);
}
__device__ __forceinline__ float gelu_tanh(float x) {
    float x3 = x * x * x;
    return 0.5f * x * (1.f + tanhf(0.7978845608028654f * (x + 0.044715f * x3)));
}
__device__ __forceinline__ float4 ld4(const float* p, int c) { return *(const float4*)(p + c); }

// ================= kernel 1: 128x128 HMMA GEMM (unchanged, proven) =================
#define TILE2  16384
#define NSTG   3
#define GSMEM  (NSTG * 2 * TILE2)    // 98304

template<int EPI, int KT>
__global__ void __launch_bounds__(256, 2)
hmma_gemm_kernel(const __nv_bfloat16* __restrict__ A, const __nv_bfloat16* __restrict__ Bt,
                 __nv_bfloat16* __restrict__ Cb,
                 const float* __restrict__ bias,
                 const float* __restrict__ ltmp, const float* __restrict__ lB,
                 const int* __restrict__ midx,
                 int N)
{
    extern __shared__ char dynsm[];
    constexpr int NCH = KT >> 6;

    int tid = threadIdx.x, lane = tid & 31, wid = tid >> 5;
    int wm = wid & 1, wn = wid >> 1;
    int brow = blockIdx.y * 128, bcol = blockIdx.x * 128;

    float acc[4][4][4];
    #pragma unroll
    for (int i = 0; i < 4; i++)
        #pragma unroll
        for (int j = 0; j < 4; j++)
            #pragma unroll
            for (int q = 0; q < 4; q++) acc[i][j][q] = 0.f;

    int lrow = tid >> 3, lcc = tid & 7;
    uint32_t soff0 = (uint32_t)(lrow * 128 + ((lcc ^ (lrow & 7)) * 16));
    const __nv_bfloat16* Ap0 = A + (size_t)(brow + lrow) * KT + lcc * 8;
    const __nv_bfloat16* Bp0 = Bt + (size_t)(bcol + lrow) * KT + lcc * 8;
    uint32_t smbase = smem_u32(dynsm);

    auto load_tiles = [&](int ch, int stage) {
        uint32_t da = smbase + (uint32_t)((stage * 2 + 0) * TILE2) + soff0;
        uint32_t db = smbase + (uint32_t)((stage * 2 + 1) * TILE2) + soff0;
        const __nv_bfloat16* Ah = Ap0 + ch * 64;
        const __nv_bfloat16* Bh = Bp0 + ch * 64;
        #pragma unroll
        for (int hh = 0; hh < 4; hh++) {
            cp16(da + hh * 4096, Ah + hh * 32 * KT);
            cp16(db + hh * 4096, Bh + hh * 32 * KT);
        }
        cp_commit();
    };

    int rsel = lane & 15, ksel = lane >> 4;
    uint32_t abase[4], bbase[2];
    #pragma unroll
    for (int mf = 0; mf < 4; mf++) {
        int ar = wm * 64 + mf * 16 + rsel;
        abase[mf] = (uint32_t)(ar * 128 + (ar & 7) * 16);
    }
    #pragma unroll
    for (int nf2 = 0; nf2 < 2; nf2++) {
        int br = wn * 32 + nf2 * 16 + rsel;
        bbase[nf2] = (uint32_t)(br * 128 + (br & 7) * 16);
    }

    load_tiles(0, 0);
    load_tiles(1, 1);

    #pragma unroll
    for (int ch = 0; ch < NCH; ch++) {
        asm volatile("cp.async.wait_group 1;");
        __syncthreads();

        uint32_t sa = smbase + (uint32_t)(((ch % NSTG) * 2 + 0) * TILE2);
        uint32_t sb = smbase + (uint32_t)(((ch % NSTG) * 2 + 1) * TILE2);

        #pragma unroll
        for (int ks = 0; ks < 4; ks++) {
            uint32_t cx = (uint32_t)((ks * 2 + ksel) * 16);
            uint32_t a[4][4];
            #pragma unroll
            for (int mf = 0; mf < 4; mf++)
                ldm_x4(a[mf][0], a[mf][1], a[mf][2], a[mf][3], sa + (abase[mf] ^ cx));
            uint32_t b[4][2];
            #pragma unroll
            for (int nf2 = 0; nf2 < 2; nf2++) {
                uint32_t r0, r1, r2, r3;
                ldm_x4(r0, r1, r2, r3, sb + (bbase[nf2] ^ cx));
                b[nf2 * 2 + 0][0] = r0; b[nf2 * 2 + 0][1] = r2;
                b[nf2 * 2 + 1][0] = r1; b[nf2 * 2 + 1][1] = r3;
            }
            #pragma unroll
            for (int mf = 0; mf < 4; mf++)
                #pragma unroll
                for (int nf = 0; nf < 4; nf++)
                    mma16816(acc[mf][nf], a[mf], b[nf]);
        }

        if (ch + 2 < NCH) load_tiles(ch + 2, (ch + 2) % NSTG);
        else              cp_commit();
    }

    float* lb_s  = (float*)dynsm;
    float* tmp_s = (float*)(dynsm + 4096);
    if (EPI == 3) {
        __syncthreads();
        int m = midx[brow / TOKPB];
        #pragma unroll
        for (int hh = 0; hh < 4; hh++) {
            int i = tid + hh * 256;
            int q = i >> 7, c = i & 127;
            lb_s[q * 128 + c] = lB[((size_t)m * RANKv + q) * N + bcol + c];
            int r = i >> 3, q2 = i & 7;
            tmp_s[r * 9 + q2] = ltmp[(size_t)(brow + r) * RANKv + q2];
        }
        __syncthreads();
    }

    int g = lane >> 2, tg = lane & 3;
    #pragma unroll
    for (int mf = 0; mf < 4; mf++) {
        int rl = wm * 64 + mf * 16 + g;
        int r0 = brow + rl;
        #pragma unroll
        for (int nf = 0; nf < 4; nf++) {
            int cl  = wn * 32 + nf * 8 + tg * 2;
            int col = bcol + cl;
            float b0 = bias[col], b1 = bias[col + 1];
            float v0 = acc[mf][nf][0] + b0, v1 = acc[mf][nf][1] + b1;
            float v2 = acc[mf][nf][2] + b0, v3 = acc[mf][nf][3] + b1;
            if (EPI == 1) {
                *(uint32_t*)(Cb + (size_t)r0 * N + col)       = pack2bf(gelu_tanh(v0), gelu_tanh(v1));
                *(uint32_t*)(Cb + (size_t)(r0 + 8) * N + col) = pack2bf(gelu_tanh(v2), gelu_tanh(v3));
            } else {
                float a00 = 0.f, a01 = 0.f, a10 = 0.f, a11 = 0.f;
                #pragma unroll
                for (int q = 0; q < 8; q++) {
                    float w0 = lb_s[q * 128 + cl], w1 = lb_s[q * 128 + cl + 1];
                    float u0 = tmp_s[rl * 9 + q], u1 = tmp_s[(rl + 8) * 9 + q];
                    a00 += u0 * w0; a01 += u0 * w1;
                    a10 += u1 * w0; a11 += u1 * w1;
                }
                *(uint32_t*)(Cb + (size_t)r0 * N + col)       = pack2bf(v0 + a00, v1 + a01);
                *(uint32_t*)(Cb + (size_t)(r0 + 8) * N + col) = pack2bf(v2 + a10, v3 + a11);
            }
        }
    }
}

// ================= kernel 2: 64x256 HMMA GEMM + residual + fused LN (+ lora) ===========
#define TA64   8192
#define TB256  32768
#define STG64  (TA64 + TB256)        // 40960
#define GSMEM2 (2 * STG64)           // 81920

template<typename TO, int KT, int DOLORA, int WRITEX>
__global__ void __launch_bounds__(256, 2)
hmma_ln_kernel(const __nv_bfloat16* __restrict__ A, const __nv_bfloat16* __restrict__ Bt,
               float* __restrict__ C,
               const float* __restrict__ bias, const float* __restrict__ gsc,
               const float* __restrict__ lnS, const float* __restrict__ lnB,
               TO* __restrict__ Hout,
               const float* __restrict__ lA, const int* __restrict__ midx,
               float* __restrict__ tmp)
{
    extern __shared__ char dynsm[];
    const int N = 256;
    constexpr int NCH = KT >> 6;

    int tid = threadIdx.x, lane = tid & 31, wid = tid >> 5;
    int wm = wid & 1, wn = wid >> 1;
    int brow = blockIdx.y * 64;

    float acc[2][8][4];
    #pragma unroll
    for (int i = 0; i < 2; i++)
        #pragma unroll
        for (int j = 0; j < 8; j++)
            #pragma unroll
            for (int q = 0; q < 4; q++) acc[i][j][q] = 0.f;

    int lrow = tid >> 3, lcc = tid & 7;
    uint32_t soff0 = (uint32_t)(lrow * 128 + ((lcc ^ (lrow & 7)) * 16));
    const __nv_bfloat16* Ap0 = A + (size_t)(brow + lrow) * KT + lcc * 8;
    const __nv_bfloat16* Bp0 = Bt + (size_t)lrow * KT + lcc * 8;
    uint32_t smbase = smem_u32(dynsm);

    auto load_tiles = [&](int ch, int stage) {
        uint32_t da = smbase + (uint32_t)(stage * STG64) + soff0;
        uint32_t db = da + TA64;
        const __nv_bfloat16* Ah = Ap0 + ch * 64;
        const __nv_bfloat16* Bh = Bp0 + ch * 64;
        #pragma unroll
        for (int hh = 0; hh < 2; hh++)
            cp16(da + hh * 4096, Ah + hh * 32 * KT);
        #pragma unroll
        for (int hh = 0; hh < 8; hh++)
            cp16(db + hh * 4096, Bh + hh * 32 * KT);
        cp_commit();
    };

    int rsel = lane & 15, ksel = lane >> 4;
    uint32_t abase[2], bbase[4];
    #pragma unroll
    for (int mf = 0; mf < 2; mf++) {
        int ar = wm * 32 + mf * 16 + rsel;
        abase[mf] = (uint32_t)(ar * 128 + (ar & 7) * 16);
    }
    #pragma unroll
    for (int nf2 = 0; nf2 < 4; nf2++) {
        int br = wn * 64 + nf2 * 16 + rsel;
        bbase[nf2] = (uint32_t)(br * 128 + (br & 7) * 16);
    }

    load_tiles(0, 0);

    for (int ch = 0; ch < NCH; ch++) {
        if (ch + 1 < NCH) {
            load_tiles(ch + 1, (ch + 1) & 1);
            asm volatile("cp.async.wait_group 1;");
        } else {
            asm volatile("cp.async.wait_group 0;");
        }
        __syncthreads();

        uint32_t sa = smbase + (uint32_t)((ch & 1) * STG64);
        uint32_t sb = sa + TA64;

        #pragma unroll
        for (int ks = 0; ks < 4; ks++) {
            uint32_t cx = (uint32_t)((ks * 2 + ksel) * 16);
            uint32_t a[2][4];
            #pragma unroll
            for (int mf = 0; mf < 2; mf++)
                ldm_x4(a[mf][0], a[mf][1], a[mf][2], a[mf][3], sa + (abase[mf] ^ cx));
            uint32_t b[8][2];
            #pragma unroll
            for (int nf2 = 0; nf2 < 4; nf2++) {
                uint32_t r0, r1, r2, r3;
                ldm_x4(r0, r1, r2, r3, sb + (bbase[nf2] ^ cx));
                b[nf2 * 2 + 0][0] = r0; b[nf2 * 2 + 0][1] = r2;
                b[nf2 * 2 + 1][0] = r1; b[nf2 * 2 + 1][1] = r3;
            }
            #pragma unroll
            for (int mf = 0; mf < 2; mf++)
                #pragma unroll
                for (int nf = 0; nf < 8; nf++)
                    mma16816(acc[mf][nf], a[mf], b[nf]);
        }
        __syncthreads();
    }

    int g = lane >> 2, tg = lane & 3;

    #pragma unroll
    for (int mf = 0; mf < 2; mf++) {
        int r0 = brow + wm * 32 + mf * 16 + g;
        #pragma unroll
        for (int nf = 0; nf < 8; nf++) {
            int col = wn * 64 + nf * 8 + tg * 2;
            float b0 = bias[col], b1 = bias[col + 1];
            float s0 = gsc[col],  s1 = gsc[col + 1];
            float2 o0 = *(float2*)(C + (size_t)r0 * N + col);
            float2 o1 = *(float2*)(C + (size_t)(r0 + 8) * N + col);
            o0.x += s0 * (acc[mf][nf][0] + b0); o0.y += s1 * (acc[mf][nf][1] + b1);
            o1.x += s0 * (acc[mf][nf][2] + b0); o1.y += s1 * (acc[mf][nf][3] + b1);
            if (WRITEX) {
                *(float2*)(C + (size_t)r0 * N + col)       = o0;
                *(float2*)(C + (size_t)(r0 + 8) * N + col) = o1;
            }
            acc[mf][nf][0] = o0.x; acc[mf][nf][1] = o0.y;
            acc[mf][nf][2] = o1.x; acc[mf][nf][3] = o1.y;
        }
    }

    float* ssum = (float*)dynsm;
    float* ssq  = ssum + 256;
    float* smu  = ssq + 256;
    float* srs  = smu + 64;
    float* laS  = srs + 64;
    float* red  = laS + 2048;
    __syncthreads();

    #pragma unroll
    for (int mf = 0; mf < 2; mf++) {
        #pragma unroll
        for (int half = 0; half < 2; half++) {
            float ps = 0.f, pq = 0.f;
            #pragma unroll
            for (int nf = 0; nf < 8; nf++) {
                float v0 = acc[mf][nf][half * 2 + 0];
                float v1 = acc[mf][nf][half * 2 + 1];
                ps += v0 + v1;
                pq += v0 * v0 + v1 * v1;
            }
            ps += __shfl_xor_sync(0xffffffffu, ps, 1);
            pq += __shfl_xor_sync(0xffffffffu, pq, 1);
            ps += __shfl_xor_sync(0xffffffffu, ps, 2);
            pq += __shfl_xor_sync(0xffffffffu, pq, 2);
            if (tg == 0) {
                int rl = wm * 32 + mf * 16 + half * 8 + g;
                ssum[rl * 4 + wn] = ps;
                ssq [rl * 4 + wn] = pq;
            }
        }
    }
    if (DOLORA) {
        int m = midx[brow / TOKPB];
        const float4* Am4 = (const float4*)(lA + (size_t)m * Hdim * RANKv);
        float4* laS4 = (float4*)laS;
        laS4[tid]       = Am4[tid];
        laS4[tid + 256] = Am4[tid + 256];
    }
    __syncthreads();
    if (tid < 64) {
        float s = ssum[tid * 4] + ssum[tid * 4 + 1] + ssum[tid * 4 + 2] + ssum[tid * 4 + 3];
        float q = ssq [tid * 4] + ssq [tid * 4 + 1] + ssq [tid * 4 + 2] + ssq [tid * 4 + 3];
        float mu = s * (1.f / 256.f);
        float var = fmaxf(q * (1.f / 256.f) - mu * mu, 0.f);
        smu[tid] = mu;
        srs[tid] = rsqrtf(var + 1e-5f);
    }
    __syncthreads();

    #pragma unroll
    for (int mf = 0; mf < 2; mf++) {
        int rl = wm * 32 + mf * 16 + g;
        float mu0 = smu[rl],     rs0 = srs[rl];
        float mu1 = smu[rl + 8], rs1 = srs[rl + 8];
        int r0 = brow + rl;
        float p0[RANKv], p1[RANKv];
        if (DOLORA) {
            #pragma unroll
            for (int r = 0; r < RANKv; r++) { p0[r] = 0.f; p1[r] = 0.f; }
        }
        #pragma unroll
        for (int nf = 0; nf < 8; nf++) {
            int col = wn * 64 + nf * 8 + tg * 2;
            float sc0 = lnS[col], sc1 = lnS[col + 1];
            float bi0 = lnB[col], bi1 = lnB[col + 1];
            float h0 = (acc[mf][nf][0] - mu0) * rs0 * sc0 + bi0;
            float h1 = (acc[mf][nf][1] - mu0) * rs0 * sc1 + bi1;
            float h2 = (acc[mf][nf][2] - mu1) * rs1 * sc0 + bi0;
            float h3 = (acc[mf][nf][3] - mu1) * rs1 * sc1 + bi1;
            if (DOLORA) {
                const float* l0 = laS + col * RANKv;
                const float* l1 = laS + (col + 1) * RANKv;
                #pragma unroll
                for (int r = 0; r < RANKv; r++) {
                    p0[r] += h0 * l0[r] + h1 * l1[r];
                    p1[r] += h2 * l0[r] + h3 * l1[r];
                }
            }
            if constexpr (sizeof(TO) == 2) {
                *(uint32_t*)((__nv_bfloat16*)Hout + (size_t)r0 * N + col)       = pack2bf(h0, h1);
                *(uint32_t*)((__nv_bfloat16*)Hout + (size_t)(r0 + 8) * N + col) = pack2bf(h2, h3);
            } else {
                *(float2*)((float*)Hout + (size_t)r0 * N + col)       = make_float2(h0, h1);
                *(float2*)((float*)Hout + (size_t)(r0 + 8) * N + col) = make_float2(h2, h3);
            }
        }
        if (DOLORA) {
            #pragma unroll
            for (int r = 0; r < RANKv; r++) {
                p0[r] += __shfl_xor_sync(0xffffffffu, p0[r], 1);
                p0[r] += __shfl_xor_sync(0xffffffffu, p0[r], 2);
                p1[r] += __shfl_xor_sync(0xffffffffu, p1[r], 1);
                p1[r] += __shfl_xor_sync(0xffffffffu, p1[r], 2);
            }
            if (tg == 0) {
                #pragma unroll
                for (int r = 0; r < RANKv; r++) {
                    red[(rl * RANKv + r) * 4 + wn]       = p0[r];
                    red[((rl + 8) * RANKv + r) * 4 + wn] = p1[r];
                }
            }
        }
    }

    if (DOLORA) {
        __syncthreads();
        #pragma unroll
        for (int hh = 0; hh < 2; hh++) {
            int i = tid + hh * 256;
            int row = i >> 3, r = i & 7;
            float4 v = *(float4*)(red + i * 4);
            tmp[(size_t)(brow + row) * RANKv + r] = v.x + v.y + v.z + v.w;
        }
    }
}

// ---------------- merged weight transpose + mask detect ----------------
__global__ void prep_kernel(const float* __restrict__ Wqkv, const float* __restrict__ Wo,
                            const float* __restrict__ W1,   const float* __restrict__ W2,
                            __nv_bfloat16* __restrict__ wt,
                            const unsigned char* __restrict__ sm,
                            const unsigned char* __restrict__ hm,
                            const unsigned char* __restrict__ gm,
                            int* __restrict__ cat)
{
    const size_t LSZ = 786432, OFF_WO = 196608, OFF_W1 = 262144, OFF_W2 = 524288;
    int bx = blockIdx.x, l = blockIdx.z;
    int tid = threadIdx.x;

    if (bx == 768) {
        if (l != 0) return;
        __shared__ int offbyte, i32bad, f32bad, f32one, fmt_s;
        if (tid == 0) { offbyte = 0; i32bad = 0; f32bad = 0; f32one = 0; }
        __syncthreads();
        const unsigned char* bufs[3] = {sm, hm, gm};
        for (int bi = 0; bi < 3; bi++) {
            const unsigned char* p = bufs[bi];
            for (int i = tid; i < NTOK; i += blockDim.x)
                if ((i & 3) != 0 && p[i] != 0) atomicOr(&offbyte, 1);
            const int*   pi = (const int*)p;
            const float* pf = (const float*)p;
            for (int i = tid; i < NTOK / 4; i += blockDim.x) {
                int iv = pi[i]; float fv = pf[i];
                if (iv != 0 && iv != 1)     atomicOr(&i32bad, 1);
                if (fv != 0.f && fv != 1.f) atomicOr(&f32bad, 1);
                if (fv == 1.f)              atomicOr(&f32one, 1);
            }
        }
        __syncthreads();
        if (tid == 0) {
            int fmt;
            if (!offbyte && !i32bad)    fmt = 1;
            else if (!f32bad && f32one) fmt = 2;
            else                        fmt = 0;
            fmt_s = fmt;
        }
        __syncthreads();
        int fmt = fmt_s;
        for (int idx = tid; idx < Bdim * Jm; idx += blockDim.x) {
            int b = idx / Jm, j = idx % Jm;
            int e = b * (Tdim * Jm) + j;
            bool sv, hv, gv;
            if (fmt == 0)      { sv = sm[e] != 0; hv = hm[e] != 0; gv = gm[e] != 0; }
            else if (fmt == 1) { sv = ((const int*)sm)[e] != 0; hv = ((const int*)hm)[e] != 0; gv = ((const int*)gm)[e] != 0; }
            else               { sv = ((const float*)sm)[e] != 0.f; hv = ((const float*)hm)[e] != 0.f; gv = ((const float*)gm)[e] != 0.f; }
            cat[idx] = sv ? 0 : (hv ? 1 : (gv ? 2 : 3));
        }
        return;
    }

    const float* src; __nv_bfloat16* dst; int K, N, tx, ty;
    if (bx < 192)      { int r = bx;       ty = r / 24, tx = r % 24; K = 256;  N = 768;
                         src = Wqkv + (size_t)l * 196608; dst = wt + l * LSZ; }
    else if (bx < 256) { int r = bx - 192; ty = r / 8,  tx = r % 8;  K = 256;  N = 256;
                         src = Wo + (size_t)l * 65536;   dst = wt + l * LSZ + OFF_WO; }
    else if (bx < 512) { int r = bx - 256; ty = r / 32, tx = r % 32; K = 256;  N = 1024;
                         src = W1 + (size_t)l * 262144;  dst = wt + l * LSZ + OFF_W1; }
    else               { int r = bx - 512; ty = r / 8,  tx = r % 8;  K = 1024; N = 256;
                         src = W2 + (size_t)l * 262144;  dst = wt + l * LSZ + OFF_W2; }

    __shared__ float t[32][33];
    int kb = ty * 32, nb = tx * 32;
    int x = tid & 31, y = tid >> 5;
    #pragma unroll
    for (int i = 0; i < 32; i += 8)
        t[y + i][x] = src[(size_t)(kb + y + i) * N + nb + x];
    __syncthreads();
    #pragma unroll
    for (int i = 0; i < 32; i += 8)
        dst[(size_t)(nb + y + i) * K + kb + x] = __float2bfloat16(t[x][y + i]);
}

// ---------------- fused embed + LN1(layer0) + lora_tmp(layer0) ----------------
__global__ void embed_ln_tmp_kernel(const float* __restrict__ act,
                                    const int* __restrict__ m_idx, const int* __restrict__ cat,
                                    const float* __restrict__ Ws, const float* __restrict__ bs,
                                    const float* __restrict__ Wh, const float* __restrict__ bh,
                                    const float* __restrict__ Wg, const float* __restrict__ Wact,
                                    const float* __restrict__ pos,
                                    const float* __restrict__ lnS, const float* __restrict__ lnB,
                                    const float* __restrict__ lA,
                                    float* __restrict__ x, __nv_bfloat16* __restrict__ h,
                                    float* __restrict__ tmp)
{
    int warp = threadIdx.x >> 5, lane = threadIdx.x & 31;
    int token = blockIdx.x * 8 + warp;
    int j = token % Jm;
    int b = token / TOKPB;
    int m = m_idx[b];
    int ct = cat[b * Jm + j];
    float a = act[token];
    const float* posr = pos + ((size_t)m * Jm + j) * Hdim;
    const float* wgr  = Wg + (size_t)m * Hdim;

    float e[8];
    #pragma unroll
    for (int half = 0; half < 2; half++) {
        int c = (lane + half * 32) * 4;
        float4 r;
        if      (ct == 0) { float4 w = ld4(Ws, c), bb = ld4(bs, c);
                            r.x = a*w.x+bb.x; r.y = a*w.y+bb.y; r.z = a*w.z+bb.z; r.w = a*w.w+bb.w; }
        else if (ct == 1) { float4 w = ld4(Wh, c), bb = ld4(bh, c);
                            r.x = a*w.x+bb.x; r.y = a*w.y+bb.y; r.z = a*w.z+bb.z; r.w = a*w.w+bb.w; }
        else if (ct == 2) { float4 w = ld4(wgr, c);
                            r.x = a*w.x; r.y = a*w.y; r.z = a*w.z; r.w = a*w.w; }
        else              { r = make_float4(0.f, 0.f, 0.f, 0.f); }
        if (ct != 3) { float4 wa = ld4(Wact, c); r.x += wa.x; r.y += wa.y; r.z += wa.z; r.w += wa.w; }
        float4 p = ld4(posr, c);
        r.x += p.x; r.y += p.y; r.z += p.z; r.w += p.w;
        e[half*4+0] = r.x; e[half*4+1] = r.y; e[half*4+2] = r.z; e[half*4+3] = r.w;
        *(float4*)(x + (size_t)token * Hdim + c) = r;
    }

    float s = 0.f;
    #pragma unroll
    for (int q = 0; q < 8; q++) s += e[q];
    #pragma unroll
    for (int o = 16; o > 0; o >>= 1) s += __shfl_xor_sync(0xffffffffu, s, o);
    float mu = s * (1.f / Hdim);
    float v = 0.f;
    #pragma unroll
    for (int q = 0; q < 8; q++) { e[q] -= mu; v += e[q] * e[q]; }
    #pragma unroll
    for (int o = 16; o > 0; o >>= 1) v += __shfl_xor_sync(0xffffffffu, v, o);
    float rs = rsqrtf(v * (1.f / Hdim) + 1e-5f);

    float hv[8];
    #pragma unroll
    for (int half = 0; half < 2; half++) {
        int c = (lane + half * 32) * 4;
        float4 sc4 = ld4(lnS, c), bi4 = ld4(lnB, c);
        hv[half*4+0] = e[half*4+0] * rs * sc4.x + bi4.x;
        hv[half*4+1] = e[half*4+1] * rs * sc4.y + bi4.y;
        hv[half*4+2] = e[half*4+2] * rs * sc4.z + bi4.z;
        hv[half*4+3] = e[half*4+3] * rs * sc4.w + bi4.w;
        *(uint2*)(h + (size_t)token * Hdim + c) =
            make_uint2(pack2bf(hv[half*4+0], hv[half*4+1]), pack2bf(hv[half*4+2], hv[half*4+3]));
    }

    const float* Am = lA + (size_t)m * Hdim * RANKv;
    float t0=0,t1=0,t2=0,t3=0,t4=0,t5=0,t6=0,t7=0;
    #pragma unroll
    for (int q = 0; q < 8; q++) {
        int c = (lane + (q >> 2) * 32) * 4 + (q & 3);
        float4 a0 = ld4(Am + (size_t)c * RANKv, 0);
        float4 a1 = ld4(Am + (size_t)c * RANKv, 4);
        float hq = hv[q];
        t0 += hq * a0.x; t1 += hq * a0.y; t2 += hq * a0.z; t3 += hq * a0.w;
        t4 += hq * a1.x; t5 += hq * a1.y; t6 += hq * a1.z; t7 += hq * a1.w;
    }
    #pragma unroll
    for (int o = 16; o > 0; o >>= 1) {
        t0 += __shfl_xor_sync(0xffffffffu, t0, o);
        t1 += __shfl_xor_sync(0xffffffffu, t1, o);
        t2 += __shfl_xor_sync(0xffffffffu, t2, o);
        t3 += __shfl_xor_sync(0xffffffffu, t3, o);
        t4 += __shfl_xor_sync(0xffffffffu, t4, o);
        t5 += __shfl_xor_sync(0xffffffffu, t5, o);
        t6 += __shfl_xor_sync(0xffffffffu, t6, o);
        t7 += __shfl_xor_sync(0xffffffffu, t7, o);
    }
    if (lane == 0) {
        float* tp = tmp + (size_t)token * RANKv;
        *(float4*)tp       = make_float4(t0, t1, t2, t3);
        *(float4*)(tp + 4) = make_float4(t4, t5, t6, t7);
    }
}

// ---------------- attention: float4 smem paths (LDS-count / 4) ----------------
#define APAD4 36    // row stride in floats: 144B, 16B-aligned

__global__ void attn_kernel(const __nv_bfloat16* __restrict__ qkv, __nv_bfloat16* __restrict__ o,
                            const int* __restrict__ m_idx)
{
    __shared__ alignas(16) float qs[Jm][APAD4];
    __shared__ alignas(16) float ks[Jm][APAD4];
    __shared__ alignas(16) float vs[Jm][APAD4];
    __shared__ float sc[Jm][Jm + 1];
    int n = blockIdx.x, head = blockIdx.y;
    int b = n >> 7;
    int nj = c_nj[m_idx[b]];
    const float scale = 0.17677669529663687f;

    // load: 24 rows x 3 mats x 16 bf162 = 1152 chunks, 9/thread
    const __nv_bfloat16* base = qkv + (size_t)n * Jm * H3 + head * DH;
    #pragma unroll
    for (int it = 0; it < 9; it++) {
        int idx = threadIdx.x + it * 128;
        int seg = idx / 384;
        int rem = idx - seg * 384;
        int j = rem >> 4, c = (rem & 15) * 2;
        __nv_bfloat162 hv2 = *(const __nv_bfloat162*)(base + (size_t)j * H3 + seg * Hdim + c);
        float2 f = __bfloat1622float2(hv2);
        if (seg == 0)      { qs[j][c] = f.x * scale; qs[j][c + 1] = f.y * scale; }
        else if (seg == 1) { ks[j][c] = f.x;         ks[j][c + 1] = f.y; }
        else               { vs[j][c] = f.x;         vs[j][c + 1] = f.y; }
    }
    __syncthreads();

    // scores: float4 dot products (8 vec-loads per row instead of 32 scalar)
    for (int idx = threadIdx.x; idx < Jm * Jm; idx += blockDim.x) {
        int i = idx / Jm, j = idx % Jm;
        bool ok = (i < nj && j < nj) || (i == j);
        float s = -3.402823466e38f;
        if (ok) {
            const float4* qr = (const float4*)&qs[i][0];
            const float4* kr = (const float4*)&ks[j][0];
            s = 0.f;
            #pragma unroll
            for (int d4 = 0; d4 < 8; d4++) {
                float4 a = qr[d4], bb = kr[d4];
                s += a.x * bb.x + a.y * bb.y + a.z * bb.z + a.w * bb.w;
            }
        }
        sc[i][j] = s;
    }
    __syncthreads();
    if (threadIdx.x < Jm) {
        int i = threadIdx.x;
        float mx = -3.402823466e38f;
        #pragma unroll
        for (int j = 0; j < Jm; j++) mx = fmaxf(mx, sc[i][j]);
        float e[Jm]; float sum = 0.f;
        #pragma unroll
        for (int j = 0; j < Jm; j++) { e[j] = expf(sc[i][j] - mx); sum += e[j]; }
        float inv = 1.f / sum;
        #pragma unroll
        for (int j = 0; j < Jm; j++) sc[i][j] = e[j] * inv;
    }
    __syncthreads();

    // AV: (i, d4) granularity — 192 items, float4 v loads
    for (int idx = threadIdx.x; idx < Jm * 8; idx += blockDim.x) {
        int i = idx >> 3, d4 = idx & 7;
        float4 a0 = make_float4(0.f, 0.f, 0.f, 0.f);
        const float* scr = &sc[i][0];
        #pragma unroll
        for (int j = 0; j < Jm; j++) {
            float w = scr[j];
            float4 v = *(const float4*)&vs[j][d4 * 4];
            a0.x += w * v.x; a0.y += w * v.y; a0.z += w * v.z; a0.w += w * v.w;
        }
        *(uint2*)(o + ((size_t)(n * Jm + i)) * Hdim + head * DH + d4 * 4) =
            make_uint2(pack2bf(a0.x, a0.y), pack2bf(a0.z, a0.w));
    }
}

// ---------------- launcher ----------------
extern "C" void kernel_launch(void* const* d_in, const int* in_sizes, int n_in,
                              void* d_out, int out_size)
{
    (void)in_sizes; (void)n_in; (void)out_size;
    const float* act   = (const float*)d_in[0];
    const unsigned char* smk = (const unsigned char*)d_in[1];
    const unsigned char* hmk = (const unsigned char*)d_in[2];
    const unsigned char* gmk = (const unsigned char*)d_in[3];
    const int*   m_idx = (const int*)d_in[6];
    const float* Ws    = (const float*)d_in[7];
    const float* bs    = (const float*)d_in[8];
    const float* Wh    = (const float*)d_in[9];
    const float* bh    = (const float*)d_in[10];
    const float* Wg    = (const float*)d_in[11];
    const float* Wact  = (const float*)d_in[12];
    const float* pos   = (const float*)d_in[13];
    const float* ln1_s = (const float*)d_in[14];
    const float* ln1_b = (const float*)d_in[15];
    const float* Wqkv  = (const float*)d_in[16];
    const float* bqkv  = (const float*)d_in[17];
    const float* loraA = (const float*)d_in[18];
    const float* loraB = (const float*)d_in[19];
    const float* Wo    = (const float*)d_in[20];
    const float* bo    = (const float*)d_in[21];
    const float* ln2_s = (const float*)d_in[22];
    const float* ln2_b = (const float*)d_in[23];
    const float* W1    = (const float*)d_in[24];
    const float* b1    = (const float*)d_in[25];
    const float* W2    = (const float*)d_in[26];
    const float* b2    = (const float*)d_in[27];
    const float* g1    = (const float*)d_in[28];
    const float* g2    = (const float*)d_in[29];
    const float* lnf_s = (const float*)d_in[30];
    const float* lnf_b = (const float*)d_in[31];
    float* out = (float*)d_out;

    float *x, *tmp; __nv_bfloat16 *h, *qkv, *ob, *midb, *wt; int *cat;
    cudaGetSymbolAddress((void**)&x,    g_x);
    cudaGetSymbolAddress((void**)&h,    g_h);
    cudaGetSymbolAddress((void**)&qkv,  g_qkv);
    cudaGetSymbolAddress((void**)&ob,   g_o);
    cudaGetSymbolAddress((void**)&midb, g_midb);
    cudaGetSymbolAddress((void**)&tmp,  g_tmp);
    cudaGetSymbolAddress((void**)&wt,   g_wt);
    cudaGetSymbolAddress((void**)&cat,  g_cat);

    cudaFuncSetAttribute((const void*)hmma_gemm_kernel<1, 256>,                  cudaFuncAttributeMaxDynamicSharedMemorySize, GSMEM);
    cudaFuncSetAttribute((const void*)hmma_gemm_kernel<3, 256>,                  cudaFuncAttributeMaxDynamicSharedMemorySize, GSMEM);
    cudaFuncSetAttribute((const void*)hmma_ln_kernel<__nv_bfloat16, 256, 0, 1>,  cudaFuncAttributeMaxDynamicSharedMemorySize, GSMEM2);
    cudaFuncSetAttribute((const void*)hmma_ln_kernel<__nv_bfloat16, 1024, 1, 1>, cudaFuncAttributeMaxDynamicSharedMemorySize, GSMEM2);
    cudaFuncSetAttribute((const void*)hmma_ln_kernel<float, 1024, 0, 0>,         cudaFuncAttributeMaxDynamicSharedMemorySize, GSMEM2);

    const size_t OFF_QKV = 0, OFF_WO = 196608, OFF_W1 = 262144, OFF_W2 = 524288, LSZ = 786432;

    prep_kernel<<<dim3(769, 1, Lnum), 256>>>(Wqkv, Wo, W1, W2, wt, smk, hmk, gmk, cat);
    embed_ln_tmp_kernel<<<NTOK / 8, 256>>>(act, m_idx, cat, Ws, bs, Wh, bh, Wg, Wact, pos,
                                           ln1_s, ln1_b, loraA, x, h, tmp);

    for (int l = 0; l < Lnum; l++) {
        hmma_gemm_kernel<3, 256><<<dim3(H3 / 128, NTOK / 128), 256, GSMEM>>>(
            h, wt + l * LSZ + OFF_QKV, qkv, bqkv + l * H3,
            tmp, loraB + (size_t)l * Mnum * RANKv * H3, m_idx, H3);
        // launch 4 on first iter: attention (ncu target)
        attn_kernel<<<dim3(NSEQ, HEADS), 128>>>(qkv, ob, m_idx);
        hmma_ln_kernel<__nv_bfloat16, 256, 0, 1><<<dim3(1, NTOK / 64), 256, GSMEM2>>>(
            ob, wt + l * LSZ + OFF_WO, x, bo + l * Hdim, g1 + l * Hdim,
            ln2_s + l * Hdim, ln2_b + l * Hdim, h, nullptr, nullptr, nullptr);
        hmma_gemm_kernel<1, 256><<<dim3(H4 / 128, NTOK / 128), 256, GSMEM>>>(
            h, wt + l * LSZ + OFF_W1, midb, b1 + l * H4,
            nullptr, nullptr, nullptr, H4);
        if (l < Lnum - 1) {
            hmma_ln_kernel<__nv_bfloat16, 1024, 1, 1><<<dim3(1, NTOK / 64), 256, GSMEM2>>>(
                midb, wt + l * LSZ + OFF_W2, x, b2 + l * Hdim, g2 + l * Hdim,
                ln1_s + (l + 1) * Hdim, ln1_b + (l + 1) * Hdim, h,
                loraA + (size_t)(l + 1) * Mnum * Hdim * RANKv, m_idx, tmp);
        } else {
            hmma_ln_kernel<float, 1024, 0, 0><<<dim3(1, NTOK / 64), 256, GSMEM2>>>(
                midb, wt + l * LSZ + OFF_W2, x, b2 + l * Hdim, g2 + l * Hdim,
                lnf_s, lnf_b, out, nullptr, nullptr, nullptr);
        }
    }
}